// round 5
// baseline (speedup 1.0000x reference)
#include <cuda_runtime.h>

#define NN 50000
#define EE 800000
#define ETOT (EE + NN)
#define FIN 128
#define NHID 256
#define HEADS 4
#define CH 64
#define NG 16
#define NEG_SLOPE 0.2f

// ---------------- scratch (device globals; no allocation allowed) ----------
__device__ float    g_xp  [(size_t)NN * NHID];   // x @ W
__device__ float    g_acc [(size_t)NN * NHID];   // aggregated messages
__device__ float    g_asrc[NN * HEADS];
__device__ float    g_adst[NN * HEADS];
__device__ float    g_elog[(size_t)ETOT * HEADS]; // logits, then exp values
__device__ unsigned g_mkey[NN * HEADS];          // monotone-mapped float max
__device__ float    g_ssum[NN * HEADS];
__device__ float    g_pmax[NG * NHID];
__device__ float    g_psum[NG * NHID];
__device__ int      g_cnt [NG];

// ---------------- helpers --------------------------------------------------
__device__ __forceinline__ float lrelu(float x) {
    return x > 0.f ? x : NEG_SLOPE * x;
}
// order-preserving float -> uint mapping (for atomicMax over signed floats)
__device__ __forceinline__ unsigned fkey(float f) {
    unsigned u = __float_as_uint(f);
    return (u & 0x80000000u) ? ~u : (u | 0x80000000u);
}
__device__ __forceinline__ float funkey(unsigned k) {
    unsigned u = (k & 0x80000000u) ? (k ^ 0x80000000u) : ~k;
    return __uint_as_float(u);
}
// vectorized fire-and-forget reduction (sm_90+): 1 instruction for 4 floats
__device__ __forceinline__ void red_add_v4(float* p, float a, float b,
                                           float c, float d) {
    asm volatile("red.global.add.v4.f32 [%0], {%1, %2, %3, %4};"
                 :: "l"(p), "f"(a), "f"(b), "f"(c), "f"(d) : "memory");
}

// ---------------- K0: zero scratch ----------------------------------------
__global__ void zero_kernel() {
    size_t i = (size_t)blockIdx.x * blockDim.x + threadIdx.x;
    if (i < (size_t)NN * NHID) g_acc[i] = 0.f;
    if (i < (size_t)NN * HEADS) { g_mkey[i] = 0u; g_ssum[i] = 0.f; }
    if (i < NG * NHID) { g_pmax[i] = 0.f; g_psum[i] = 0.f; }
    if (i < NG) g_cnt[i] = 0;
}

// ---------------- K1: SGEMM  xp = x @ W  (M=50000, N=256, K=128) -----------
// 64x64 tile, BK=16, 256 threads, 4x4 microtile.
__global__ void gemm_kernel(const float* __restrict__ A,
                            const float* __restrict__ B) {
    __shared__ float As[16][64];
    __shared__ float Bs[16][64];

    const int tid = threadIdx.x;          // 0..255
    const int tx = tid & 15;
    const int ty = tid >> 4;
    const int bm = blockIdx.x * 64;
    const int bn = blockIdx.y * 64;

    const int arow  = tid >> 2;           // 0..63
    const int acol4 = (tid & 3) * 4;      // 0,4,8,12
    const int brow  = tid >> 4;           // 0..15
    const int bcol4 = (tid & 15) * 4;     // 0..60

    float acc[4][4];
#pragma unroll
    for (int i = 0; i < 4; i++)
#pragma unroll
        for (int j = 0; j < 4; j++) acc[i][j] = 0.f;

    for (int k0 = 0; k0 < FIN; k0 += 16) {
        const int gm = bm + arow;
        float4 av = make_float4(0.f, 0.f, 0.f, 0.f);
        if (gm < NN)
            av = *(const float4*)(A + (size_t)gm * FIN + k0 + acol4);
        As[acol4 + 0][arow] = av.x;
        As[acol4 + 1][arow] = av.y;
        As[acol4 + 2][arow] = av.z;
        As[acol4 + 3][arow] = av.w;

        float4 bv = *(const float4*)(B + (size_t)(k0 + brow) * NHID + bn + bcol4);
        *(float4*)&Bs[brow][bcol4] = bv;
        __syncthreads();

#pragma unroll
        for (int k = 0; k < 16; k++) {
            float af[4], bf[4];
#pragma unroll
            for (int i = 0; i < 4; i++) af[i] = As[k][ty * 4 + i];
#pragma unroll
            for (int j = 0; j < 4; j++) bf[j] = Bs[k][tx * 4 + j];
#pragma unroll
            for (int i = 0; i < 4; i++)
#pragma unroll
                for (int j = 0; j < 4; j++) acc[i][j] = fmaf(af[i], bf[j], acc[i][j]);
        }
        __syncthreads();
    }

#pragma unroll
    for (int i = 0; i < 4; i++) {
        const int gm = bm + ty * 4 + i;
        if (gm < NN) {
            float4 v = make_float4(acc[i][0], acc[i][1], acc[i][2], acc[i][3]);
            *(float4*)(g_xp + (size_t)gm * NHID + bn + tx * 4) = v;
        }
    }
}

// ---------------- K2: attention coefficients a_src, a_dst ------------------
// One warp per node; lane handles 8 channels.
__global__ void acoef_kernel(const float* __restrict__ att_src,
                             const float* __restrict__ att_dst) {
    const int gwarp = (blockIdx.x * blockDim.x + threadIdx.x) >> 5;
    const int lane  = threadIdx.x & 31;
    if (gwarp >= NN) return;

    const float4* xr = (const float4*)(g_xp + (size_t)gwarp * NHID);
    float4 v0 = xr[lane * 2 + 0];
    float4 v1 = xr[lane * 2 + 1];

    const int head = lane >> 3;
    const int coff = (lane & 7) * 8;  // channel offset within head
    const float4* s4 = (const float4*)(att_src + head * CH + coff);
    const float4* d4 = (const float4*)(att_dst + head * CH + coff);
    float4 s0 = s4[0], s1 = s4[1];
    float4 d0 = d4[0], d1 = d4[1];

    float ps = v0.x * s0.x + v0.y * s0.y + v0.z * s0.z + v0.w * s0.w
             + v1.x * s1.x + v1.y * s1.y + v1.z * s1.z + v1.w * s1.w;
    float pd = v0.x * d0.x + v0.y * d0.y + v0.z * d0.z + v0.w * d0.w
             + v1.x * d1.x + v1.y * d1.y + v1.z * d1.z + v1.w * d1.w;

#pragma unroll
    for (int o = 1; o < 8; o <<= 1) {
        ps += __shfl_xor_sync(0xFFFFFFFFu, ps, o);
        pd += __shfl_xor_sync(0xFFFFFFFFu, pd, o);
    }
    if ((lane & 7) == 0) {
        g_asrc[gwarp * HEADS + head] = ps;
        g_adst[gwarp * HEADS + head] = pd;
    }
}

// ---------------- K3: per-edge logits + segment max ------------------------
__global__ void edge_max_kernel(const int* __restrict__ ei) {
    const int e = blockIdx.x * blockDim.x + threadIdx.x;
    if (e >= ETOT) return;
    int s, d;
    if (e < EE) { s = ei[e]; d = ei[EE + e]; }
    else        { s = d = e - EE; }

    float4 as = *(const float4*)(g_asrc + s * HEADS);
    float4 ad = *(const float4*)(g_adst + d * HEADS);
    float4 l;
    l.x = lrelu(as.x + ad.x);
    l.y = lrelu(as.y + ad.y);
    l.z = lrelu(as.z + ad.z);
    l.w = lrelu(as.w + ad.w);
    *(float4*)(g_elog + (size_t)e * HEADS) = l;

    unsigned* mp = g_mkey + d * HEADS;
    atomicMax(mp + 0, fkey(l.x));
    atomicMax(mp + 1, fkey(l.y));
    atomicMax(mp + 2, fkey(l.z));
    atomicMax(mp + 3, fkey(l.w));
}

// ---------------- K4: per-edge exp + segment sum ---------------------------
__global__ void edge_exp_kernel(const int* __restrict__ ei) {
    const int e = blockIdx.x * blockDim.x + threadIdx.x;
    if (e >= ETOT) return;
    int d;
    if (e < EE) d = ei[EE + e]; else d = e - EE;

    float4 l = *(const float4*)(g_elog + (size_t)e * HEADS);
    uint4 mk = *(const uint4*)(g_mkey + d * HEADS);
    float4 ev;
    ev.x = expf(l.x - funkey(mk.x));
    ev.y = expf(l.y - funkey(mk.y));
    ev.z = expf(l.z - funkey(mk.z));
    ev.w = expf(l.w - funkey(mk.w));
    *(float4*)(g_elog + (size_t)e * HEADS) = ev;

    red_add_v4(g_ssum + d * HEADS, ev.x, ev.y, ev.z, ev.w);
}

// ---------------- K5: scatter  acc[dst] += alpha * xp[src] -----------------
// One warp per edge; lane owns 8 contiguous channels (one head each).
// Two red.global.add.v4.f32 per lane (instead of 8 scalar atomics).
__global__ void edge_scatter_kernel(const int* __restrict__ ei) {
    const int gwarp = (int)(((size_t)blockIdx.x * blockDim.x + threadIdx.x) >> 5);
    const int lane  = threadIdx.x & 31;
    if (gwarp >= ETOT) return;
    int s, d;
    if (gwarp < EE) { s = ei[gwarp]; d = ei[EE + gwarp]; }
    else            { s = d = gwarp - EE; }

    const int head = lane >> 3;
    const float ev = g_elog[(size_t)gwarp * HEADS + head];
    const float ss = g_ssum[d * HEADS + head];
    const float alpha = ev / (ss + 1e-16f);

    const float4* xs = (const float4*)(g_xp + (size_t)s * NHID) + lane * 2;
    float4 v0 = xs[0], v1 = xs[1];
    float* op = g_acc + (size_t)d * NHID + lane * 8;
    red_add_v4(op + 0, v0.x * alpha, v0.y * alpha, v0.z * alpha, v0.w * alpha);
    red_add_v4(op + 4, v1.x * alpha, v1.y * alpha, v1.z * alpha, v1.w * alpha);
}

// ---------------- K6: bias + ReLU + per-graph max/mean pooling -------------
#define POOL_NODES 256
__global__ void pool_kernel(const float* __restrict__ bias,
                            const int* __restrict__ batch) {
    const int c  = threadIdx.x;               // channel 0..255
    const int n0 = blockIdx.x * POOL_NODES;
    const int n1 = min(n0 + POOL_NODES, NN);
    const int cnt_local = n1 - n0;

    __shared__ int sb[POOL_NODES];
    for (int i = threadIdx.x; i < cnt_local; i += blockDim.x)
        sb[i] = batch[n0 + i];
    __syncthreads();

    const float b = bias[c];
    int curg = sb[0];
    float mx = 0.f, sm = 0.f;
    int cnt = 0;

    for (int i = 0; i < cnt_local; i++) {
        const int g = sb[i];
        if (g != curg) {
            atomicMax((int*)&g_pmax[curg * NHID + c], __float_as_int(mx));
            atomicAdd(&g_psum[curg * NHID + c], sm);
            if (c == 0) atomicAdd(&g_cnt[curg], cnt);
            curg = g; mx = 0.f; sm = 0.f; cnt = 0;
        }
        float h = g_acc[(size_t)(n0 + i) * NHID + c] + b;
        h = fmaxf(h, 0.f);
        mx = fmaxf(mx, h);
        sm += h;
        cnt++;
    }
    atomicMax((int*)&g_pmax[curg * NHID + c], __float_as_int(mx));
    atomicAdd(&g_psum[curg * NHID + c], sm);
    if (c == 0) atomicAdd(&g_cnt[curg], cnt);
}

// ---------------- K7: write output [NG, 2*NHID] ----------------------------
__global__ void final_kernel(float* __restrict__ out) {
    const int i = blockIdx.x * blockDim.x + threadIdx.x;
    if (i >= NG * NHID) return;
    const int g = i >> 8;
    const int c = i & 255;
    out[g * (2 * NHID) + c] = g_pmax[i];
    out[g * (2 * NHID) + NHID + c] = g_psum[i] / ((float)g_cnt[g] + 1e-16f);
}

// ---------------- launcher -------------------------------------------------
extern "C" void kernel_launch(void* const* d_in, const int* in_sizes, int n_in,
                              void* d_out, int out_size) {
    const float* x       = (const float*)d_in[0];
    const int*   ei      = (const int*)d_in[1];
    const int*   batch   = (const int*)d_in[2];
    const float* W       = (const float*)d_in[3];
    const float* att_src = (const float*)d_in[4];
    const float* att_dst = (const float*)d_in[5];
    const float* bias    = (const float*)d_in[6];
    float* out = (float*)d_out;

    // K0: zero scratch (covers NN*NHID = 12.8M elements)
    {
        int threads = 256;
        int blocks = (int)(((size_t)NN * NHID + threads - 1) / threads);
        zero_kernel<<<blocks, threads>>>();
    }
    // K1: SGEMM
    {
        dim3 grid((NN + 63) / 64, NHID / 64);
        gemm_kernel<<<grid, 256>>>(x, W);
    }
    // K2: attention coefficients (one warp per node)
    {
        int threads = 256;
        int blocks = (NN * 32 + threads - 1) / threads;
        acoef_kernel<<<blocks, threads>>>(att_src, att_dst);
    }
    // K3: logits + segment max
    {
        int threads = 256;
        int blocks = (ETOT + threads - 1) / threads;
        edge_max_kernel<<<blocks, threads>>>(ei);
    }
    // K4: exp + segment sum
    {
        int threads = 256;
        int blocks = (ETOT + threads - 1) / threads;
        edge_exp_kernel<<<blocks, threads>>>(ei);
    }
    // K5: scatter (one warp per edge)
    {
        int threads = 256;
        long long total = (long long)ETOT * 32;
        int blocks = (int)((total + threads - 1) / threads);
        edge_scatter_kernel<<<blocks, threads>>>(ei);
    }
    // K6: pooling
    {
        int blocks = (NN + POOL_NODES - 1) / POOL_NODES;
        pool_kernel<<<blocks, 256>>>(bias, batch);
    }
    // K7: output
    {
        int threads = 256;
        int blocks = (NG * NHID + threads - 1) / threads;
        final_kernel<<<blocks, threads>>>(out);
    }
}

// round 6
// speedup vs baseline: 1.2102x; 1.2102x over previous
#include <cuda_runtime.h>
#include <math_constants.h>

#define NN 50000
#define EE 800000
#define ETOT (EE + NN)
#define FIN 128
#define NHID 256
#define HEADS 4
#define CH 64
#define NG 16
#define NEG_SLOPE 0.2f

// ---------------- scratch (device globals; no allocation allowed) ----------
__device__ float g_xp  [(size_t)NN * NHID];   // x @ W
__device__ float g_acc [(size_t)NN * NHID];   // h = relu(agg + bias)
__device__ float g_asrc[NN * HEADS];
__device__ float g_adst[NN * HEADS];
__device__ int   g_deg [NN];
__device__ int   g_rowptr[NN + 1];
__device__ int   g_wp  [NN];
__device__ int   g_csrc[ETOT];
__device__ float g_pmax[NG * NHID];
__device__ float g_psum[NG * NHID];
__device__ int   g_cnt [NG];

// ---------------- helpers --------------------------------------------------
__device__ __forceinline__ float lrelu(float x) {
    return x > 0.f ? x : NEG_SLOPE * x;
}

// ---------------- K0: zero small scratch -----------------------------------
__global__ void zero_kernel() {
    int i = blockIdx.x * blockDim.x + threadIdx.x;
    if (i < NN) g_deg[i] = 0;
    if (i < NG * NHID) { g_pmax[i] = 0.f; g_psum[i] = 0.f; }
    if (i < NG) g_cnt[i] = 0;
}

// ---------------- K1: SGEMM  xp = x @ W  (M=50000, N=256, K=128) -----------
// 64x64 tile, BK=16, 256 threads, 4x4 microtile. (unchanged from R5)
__global__ void gemm_kernel(const float* __restrict__ A,
                            const float* __restrict__ B) {
    __shared__ float As[16][64];
    __shared__ float Bs[16][64];

    const int tid = threadIdx.x;          // 0..255
    const int tx = tid & 15;
    const int ty = tid >> 4;
    const int bm = blockIdx.x * 64;
    const int bn = blockIdx.y * 64;

    const int arow  = tid >> 2;           // 0..63
    const int acol4 = (tid & 3) * 4;      // 0,4,8,12
    const int brow  = tid >> 4;           // 0..15
    const int bcol4 = (tid & 15) * 4;     // 0..60

    float acc[4][4];
#pragma unroll
    for (int i = 0; i < 4; i++)
#pragma unroll
        for (int j = 0; j < 4; j++) acc[i][j] = 0.f;

    for (int k0 = 0; k0 < FIN; k0 += 16) {
        const int gm = bm + arow;
        float4 av = make_float4(0.f, 0.f, 0.f, 0.f);
        if (gm < NN)
            av = *(const float4*)(A + (size_t)gm * FIN + k0 + acol4);
        As[acol4 + 0][arow] = av.x;
        As[acol4 + 1][arow] = av.y;
        As[acol4 + 2][arow] = av.z;
        As[acol4 + 3][arow] = av.w;

        float4 bv = *(const float4*)(B + (size_t)(k0 + brow) * NHID + bn + bcol4);
        *(float4*)&Bs[brow][bcol4] = bv;
        __syncthreads();

#pragma unroll
        for (int k = 0; k < 16; k++) {
            float af[4], bf[4];
#pragma unroll
            for (int i = 0; i < 4; i++) af[i] = As[k][ty * 4 + i];
#pragma unroll
            for (int j = 0; j < 4; j++) bf[j] = Bs[k][tx * 4 + j];
#pragma unroll
            for (int i = 0; i < 4; i++)
#pragma unroll
                for (int j = 0; j < 4; j++) acc[i][j] = fmaf(af[i], bf[j], acc[i][j]);
        }
        __syncthreads();
    }

#pragma unroll
    for (int i = 0; i < 4; i++) {
        const int gm = bm + ty * 4 + i;
        if (gm < NN) {
            float4 v = make_float4(acc[i][0], acc[i][1], acc[i][2], acc[i][3]);
            *(float4*)(g_xp + (size_t)gm * NHID + bn + tx * 4) = v;
        }
    }
}

// ---------------- K2: attention coefficients a_src, a_dst ------------------
__global__ void acoef_kernel(const float* __restrict__ att_src,
                             const float* __restrict__ att_dst) {
    const int gwarp = (blockIdx.x * blockDim.x + threadIdx.x) >> 5;
    const int lane  = threadIdx.x & 31;
    if (gwarp >= NN) return;

    const float4* xr = (const float4*)(g_xp + (size_t)gwarp * NHID);
    float4 v0 = xr[lane * 2 + 0];
    float4 v1 = xr[lane * 2 + 1];

    const int head = lane >> 3;
    const int coff = (lane & 7) * 8;
    const float4* s4 = (const float4*)(att_src + head * CH + coff);
    const float4* d4 = (const float4*)(att_dst + head * CH + coff);
    float4 s0 = s4[0], s1 = s4[1];
    float4 d0 = d4[0], d1 = d4[1];

    float ps = v0.x * s0.x + v0.y * s0.y + v0.z * s0.z + v0.w * s0.w
             + v1.x * s1.x + v1.y * s1.y + v1.z * s1.z + v1.w * s1.w;
    float pd = v0.x * d0.x + v0.y * d0.y + v0.z * d0.z + v0.w * d0.w
             + v1.x * d1.x + v1.y * d1.y + v1.z * d1.z + v1.w * d1.w;

#pragma unroll
    for (int o = 1; o < 8; o <<= 1) {
        ps += __shfl_xor_sync(0xFFFFFFFFu, ps, o);
        pd += __shfl_xor_sync(0xFFFFFFFFu, pd, o);
    }
    if ((lane & 7) == 0) {
        g_asrc[gwarp * HEADS + head] = ps;
        g_adst[gwarp * HEADS + head] = pd;
    }
}

// ---------------- K3: degree histogram -------------------------------------
__global__ void hist_kernel(const int* __restrict__ ei) {
    const int e = blockIdx.x * blockDim.x + threadIdx.x;
    if (e >= ETOT) return;
    const int d = (e < EE) ? ei[EE + e] : (e - EE);
    atomicAdd(g_deg + d, 1);
}

// ---------------- K4: exclusive scan -> row_ptr (single block) -------------
#define SCAN_T 1024
__global__ void scan_kernel() {
    __shared__ int ssum[SCAN_T];
    const int t = threadIdx.x;
    const int chunk = (NN + SCAN_T - 1) / SCAN_T;   // 49
    const int lo = t * chunk;
    const int hi = min(lo + chunk, NN);

    int s = 0;
    for (int i = lo; i < hi; i++) s += g_deg[i];
    ssum[t] = s;
    __syncthreads();

    // Hillis-Steele inclusive scan
    for (int off = 1; off < SCAN_T; off <<= 1) {
        int v = (t >= off) ? ssum[t - off] : 0;
        __syncthreads();
        ssum[t] += v;
        __syncthreads();
    }

    int run = (t == 0) ? 0 : ssum[t - 1];
    for (int i = lo; i < hi; i++) {
        g_rowptr[i] = run;
        g_wp[i] = run;
        run += g_deg[i];
    }
    if (t == SCAN_T - 1) g_rowptr[NN] = ETOT;
}

// ---------------- K5: CSR fill (src ids grouped by dst) --------------------
__global__ void fill_kernel(const int* __restrict__ ei) {
    const int e = blockIdx.x * blockDim.x + threadIdx.x;
    if (e >= ETOT) return;
    int s, d;
    if (e < EE) { s = ei[e]; d = ei[EE + e]; }
    else        { s = d = e - EE; }
    const int pos = atomicAdd(g_wp + d, 1);
    g_csrc[pos] = s;
}

// ---------------- K6: warp-per-dst softmax + aggregate ---------------------
// Pass A: per-head max over incoming edges (strided lanes + shfl reduce).
// Pass B: per-head exp-sum.
// Pass C: sequential edge loop; lanes own 8 channels; acc in registers.
__global__ void agg_kernel(const float* __restrict__ bias) {
    const int w    = (int)(((size_t)blockIdx.x * blockDim.x + threadIdx.x) >> 5);
    const int lane = threadIdx.x & 31;
    if (w >= NN) return;
    const int d  = w;
    const int e0 = g_rowptr[d];
    const int e1 = g_rowptr[d + 1];

    const float4 ad = *(const float4*)(g_adst + 4 * d);

    // ---- pass A: max logit per head ----
    float4 m = make_float4(-CUDART_INF_F, -CUDART_INF_F,
                           -CUDART_INF_F, -CUDART_INF_F);
    for (int e = e0 + lane; e < e1; e += 32) {
        const int s = g_csrc[e];
        const float4 as = *(const float4*)(g_asrc + 4 * s);
        m.x = fmaxf(m.x, lrelu(as.x + ad.x));
        m.y = fmaxf(m.y, lrelu(as.y + ad.y));
        m.z = fmaxf(m.z, lrelu(as.z + ad.z));
        m.w = fmaxf(m.w, lrelu(as.w + ad.w));
    }
#pragma unroll
    for (int o = 16; o >= 1; o >>= 1) {
        m.x = fmaxf(m.x, __shfl_xor_sync(0xFFFFFFFFu, m.x, o));
        m.y = fmaxf(m.y, __shfl_xor_sync(0xFFFFFFFFu, m.y, o));
        m.z = fmaxf(m.z, __shfl_xor_sync(0xFFFFFFFFu, m.z, o));
        m.w = fmaxf(m.w, __shfl_xor_sync(0xFFFFFFFFu, m.w, o));
    }

    // ---- pass B: exp-sum per head ----
    float4 sm = make_float4(0.f, 0.f, 0.f, 0.f);
    for (int e = e0 + lane; e < e1; e += 32) {
        const int s = g_csrc[e];
        const float4 as = *(const float4*)(g_asrc + 4 * s);
        sm.x += expf(lrelu(as.x + ad.x) - m.x);
        sm.y += expf(lrelu(as.y + ad.y) - m.y);
        sm.z += expf(lrelu(as.z + ad.z) - m.z);
        sm.w += expf(lrelu(as.w + ad.w) - m.w);
    }
#pragma unroll
    for (int o = 16; o >= 1; o >>= 1) {
        sm.x += __shfl_xor_sync(0xFFFFFFFFu, sm.x, o);
        sm.y += __shfl_xor_sync(0xFFFFFFFFu, sm.y, o);
        sm.z += __shfl_xor_sync(0xFFFFFFFFu, sm.z, o);
        sm.w += __shfl_xor_sync(0xFFFFFFFFu, sm.w, o);
    }

    // ---- per-lane head scalars ----
    const int head = lane >> 3;
    const float mh  = (head == 0) ? m.x : (head == 1) ? m.y
                    : (head == 2) ? m.z : m.w;
    const float shs = (head == 0) ? sm.x : (head == 1) ? sm.y
                    : (head == 2) ? sm.z : sm.w;
    const float adh = (head == 0) ? ad.x : (head == 1) ? ad.y
                    : (head == 2) ? ad.z : ad.w;
    const float inv = 1.f / (shs + 1e-16f);

    // ---- pass C: weighted gather-accumulate ----
    float a0 = 0.f, a1 = 0.f, a2 = 0.f, a3 = 0.f;
    float a4 = 0.f, a5 = 0.f, a6 = 0.f, a7 = 0.f;
    const float4* xpb = (const float4*)g_xp;

    int s_cur = g_csrc[e0];               // e1 > e0 always (self-loop)
    for (int e = e0; e < e1; e++) {
        const int s_nxt = (e + 1 < e1) ? g_csrc[e + 1] : 0;  // prefetch
        const float4 as = *(const float4*)(g_asrc + 4 * s_cur);
        const float ash = (head == 0) ? as.x : (head == 1) ? as.y
                        : (head == 2) ? as.z : as.w;
        const float wgt = expf(lrelu(ash + adh) - mh) * inv;
        const float4* xr = xpb + (size_t)s_cur * (NHID / 4) + lane * 2;
        const float4 v0 = xr[0];
        const float4 v1 = xr[1];
        a0 = fmaf(wgt, v0.x, a0);
        a1 = fmaf(wgt, v0.y, a1);
        a2 = fmaf(wgt, v0.z, a2);
        a3 = fmaf(wgt, v0.w, a3);
        a4 = fmaf(wgt, v1.x, a4);
        a5 = fmaf(wgt, v1.y, a5);
        a6 = fmaf(wgt, v1.z, a6);
        a7 = fmaf(wgt, v1.w, a7);
        s_cur = s_nxt;
    }

    // ---- bias + relu + store h ----
    const float4 b0 = *(const float4*)(bias + lane * 8);
    const float4 b1 = *(const float4*)(bias + lane * 8 + 4);
    float4 h0, h1;
    h0.x = fmaxf(a0 + b0.x, 0.f);
    h0.y = fmaxf(a1 + b0.y, 0.f);
    h0.z = fmaxf(a2 + b0.z, 0.f);
    h0.w = fmaxf(a3 + b0.w, 0.f);
    h1.x = fmaxf(a4 + b1.x, 0.f);
    h1.y = fmaxf(a5 + b1.y, 0.f);
    h1.z = fmaxf(a6 + b1.z, 0.f);
    h1.w = fmaxf(a7 + b1.w, 0.f);
    float4* op = (float4*)(g_acc + (size_t)d * NHID + lane * 8);
    op[0] = h0;
    op[1] = h1;
}

// ---------------- K7: per-graph max/mean pooling (h already in g_acc) ------
#define POOL_NODES 256
__global__ void pool_kernel(const int* __restrict__ batch) {
    const int c  = threadIdx.x;               // channel 0..255
    const int n0 = blockIdx.x * POOL_NODES;
    const int n1 = min(n0 + POOL_NODES, NN);
    const int cnt_local = n1 - n0;

    __shared__ int sb[POOL_NODES];
    for (int i = threadIdx.x; i < cnt_local; i += blockDim.x)
        sb[i] = batch[n0 + i];
    __syncthreads();

    int curg = sb[0];
    float mx = 0.f, sm = 0.f;
    int cnt = 0;

    for (int i = 0; i < cnt_local; i++) {
        const int g = sb[i];
        if (g != curg) {
            atomicMax((int*)&g_pmax[curg * NHID + c], __float_as_int(mx));
            atomicAdd(&g_psum[curg * NHID + c], sm);
            if (c == 0) atomicAdd(&g_cnt[curg], cnt);
            curg = g; mx = 0.f; sm = 0.f; cnt = 0;
        }
        const float h = g_acc[(size_t)(n0 + i) * NHID + c];  // h >= 0
        mx = fmaxf(mx, h);
        sm += h;
        cnt++;
    }
    atomicMax((int*)&g_pmax[curg * NHID + c], __float_as_int(mx));
    atomicAdd(&g_psum[curg * NHID + c], sm);
    if (c == 0) atomicAdd(&g_cnt[curg], cnt);
}

// ---------------- K8: write output [NG, 2*NHID] ----------------------------
__global__ void final_kernel(float* __restrict__ out) {
    const int i = blockIdx.x * blockDim.x + threadIdx.x;
    if (i >= NG * NHID) return;
    const int g = i >> 8;
    const int c = i & 255;
    out[g * (2 * NHID) + c] = g_pmax[i];
    out[g * (2 * NHID) + NHID + c] = g_psum[i] / ((float)g_cnt[g] + 1e-16f);
}

// ---------------- launcher -------------------------------------------------
extern "C" void kernel_launch(void* const* d_in, const int* in_sizes, int n_in,
                              void* d_out, int out_size) {
    const float* x       = (const float*)d_in[0];
    const int*   ei      = (const int*)d_in[1];
    const int*   batch   = (const int*)d_in[2];
    const float* W       = (const float*)d_in[3];
    const float* att_src = (const float*)d_in[4];
    const float* att_dst = (const float*)d_in[5];
    const float* bias    = (const float*)d_in[6];
    float* out = (float*)d_out;

    // K0: zero small scratch
    zero_kernel<<<(NN + 255) / 256, 256>>>();
    // K1: SGEMM
    {
        dim3 grid((NN + 63) / 64, NHID / 64);
        gemm_kernel<<<grid, 256>>>(x, W);
    }
    // K2: attention coefficients (one warp per node)
    acoef_kernel<<<(NN * 32 + 255) / 256, 256>>>(att_src, att_dst);
    // K3: degree histogram
    hist_kernel<<<(ETOT + 255) / 256, 256>>>(ei);
    // K4: exclusive scan
    scan_kernel<<<1, SCAN_T>>>();
    // K5: CSR fill
    fill_kernel<<<(ETOT + 255) / 256, 256>>>(ei);
    // K6: warp-per-dst aggregation (softmax + gather, no atomics)
    {
        long long total = (long long)NN * 32;
        agg_kernel<<<(int)((total + 255) / 256), 256>>>(bias);
    }
    // K7: pooling
    pool_kernel<<<(NN + POOL_NODES - 1) / POOL_NODES, 256>>>(batch);
    // K8: output
    final_kernel<<<(NG * NHID + 255) / 256, 256>>>(out);
}

// round 8
// speedup vs baseline: 1.2528x; 1.0353x over previous
#include <cuda_runtime.h>
#include <cuda_fp16.h>
#include <math_constants.h>

#define NN 50000
#define EE 800000
#define ETOT (EE + NN)
#define FIN 128
#define NHID 256
#define HEADS 4
#define CH 64
#define NG 16
#define NEG_SLOPE 0.2f

// ---------------- scratch (device globals; no allocation allowed) ----------
__device__ float  g_xp  [(size_t)NN * NHID];   // x @ W (fp32, for acoef)
__device__ __half g_xph [(size_t)NN * NHID];   // x @ W (fp16, for gather)
__device__ float  g_acc [(size_t)NN * NHID];   // h = relu(agg + bias)
__device__ float  g_asrc[NN * HEADS];
__device__ float  g_adst[NN * HEADS];
__device__ int    g_deg [NN];
__device__ int    g_rowptr[NN + 1];
__device__ int    g_wp  [NN];
__device__ int    g_csrc[ETOT];
__device__ float  g_pmax[NG * NHID];
__device__ float  g_psum[NG * NHID];
__device__ int    g_cnt [NG];

// ---------------- helpers --------------------------------------------------
__device__ __forceinline__ float lrelu(float x) {
    return x > 0.f ? x : NEG_SLOPE * x;
}

// ---------------- K0: zero small scratch -----------------------------------
__global__ void zero_kernel() {
    int i = blockIdx.x * blockDim.x + threadIdx.x;
    if (i < NN) g_deg[i] = 0;
    if (i < NG * NHID) { g_pmax[i] = 0.f; g_psum[i] = 0.f; }
    if (i < NG) g_cnt[i] = 0;
}

// ---------------- K1: SGEMM  xp = x @ W  (M=50000, N=256, K=128) -----------
// 128x128 tile, BK=8, 256 threads, 8x8 microtile. Epilogue writes fp32 + fp16.
#define BM 128
#define BN 128
#define BK 8
#define ASPAD 132   // 128 + 4 pad (rows stay 16B aligned: 132*4=528, 528%16==0)
__global__ void __launch_bounds__(256, 2)
gemm_kernel(const float* __restrict__ A, const float* __restrict__ B) {
    __shared__ float As[BK][ASPAD];
    __shared__ float Bs[BK][BN];

    const int tid = threadIdx.x;          // 0..255
    const int tx = tid & 15;              // col group 0..15
    const int ty = tid >> 4;              // row group 0..15
    const int bm = blockIdx.x * BM;
    const int bn = blockIdx.y * BN;

    const int arow  = tid >> 1;           // 0..127
    const int acol4 = (tid & 1) * 4;      // 0 or 4
    const int brow  = tid >> 5;           // 0..7
    const int bcol4 = (tid & 31) * 4;     // 0..124

    float acc[8][8];
#pragma unroll
    for (int i = 0; i < 8; i++)
#pragma unroll
        for (int j = 0; j < 8; j++) acc[i][j] = 0.f;

    for (int k0 = 0; k0 < FIN; k0 += BK) {
        const int gm = bm + arow;
        float4 av = make_float4(0.f, 0.f, 0.f, 0.f);
        if (gm < NN)
            av = *(const float4*)(A + (size_t)gm * FIN + k0 + acol4);
        As[acol4 + 0][arow] = av.x;
        As[acol4 + 1][arow] = av.y;
        As[acol4 + 2][arow] = av.z;
        As[acol4 + 3][arow] = av.w;

        *(float4*)&Bs[brow][bcol4] =
            *(const float4*)(B + (size_t)(k0 + brow) * NHID + bn + bcol4);
        __syncthreads();

#pragma unroll
        for (int k = 0; k < BK; k++) {
            float af[8], bf[8];
            *(float4*)&af[0] = *(const float4*)&As[k][ty * 8 + 0];
            *(float4*)&af[4] = *(const float4*)&As[k][ty * 8 + 4];
            *(float4*)&bf[0] = *(const float4*)&Bs[k][tx * 8 + 0];
            *(float4*)&bf[4] = *(const float4*)&Bs[k][tx * 8 + 4];
#pragma unroll
            for (int i = 0; i < 8; i++)
#pragma unroll
                for (int j = 0; j < 8; j++)
                    acc[i][j] = fmaf(af[i], bf[j], acc[i][j]);
        }
        __syncthreads();
    }

#pragma unroll
    for (int i = 0; i < 8; i++) {
        const int gm = bm + ty * 8 + i;
        if (gm < NN) {
            float* op = g_xp + (size_t)gm * NHID + bn + tx * 8;
            *(float4*)(op + 0) = make_float4(acc[i][0], acc[i][1], acc[i][2], acc[i][3]);
            *(float4*)(op + 4) = make_float4(acc[i][4], acc[i][5], acc[i][6], acc[i][7]);
            __half2 h[4];
            h[0] = __floats2half2_rn(acc[i][0], acc[i][1]);
            h[1] = __floats2half2_rn(acc[i][2], acc[i][3]);
            h[2] = __floats2half2_rn(acc[i][4], acc[i][5]);
            h[3] = __floats2half2_rn(acc[i][6], acc[i][7]);
            *(uint4*)(g_xph + (size_t)gm * NHID + bn + tx * 8) = *(uint4*)h;
        }
    }
}

// ---------------- K2: attention coefficients a_src, a_dst ------------------
__global__ void acoef_kernel(const float* __restrict__ att_src,
                             const float* __restrict__ att_dst) {
    const int gwarp = (blockIdx.x * blockDim.x + threadIdx.x) >> 5;
    const int lane  = threadIdx.x & 31;
    if (gwarp >= NN) return;

    const float4* xr = (const float4*)(g_xp + (size_t)gwarp * NHID);
    float4 v0 = xr[lane * 2 + 0];
    float4 v1 = xr[lane * 2 + 1];

    const int head = lane >> 3;
    const int coff = (lane & 7) * 8;
    const float4* s4 = (const float4*)(att_src + head * CH + coff);
    const float4* d4 = (const float4*)(att_dst + head * CH + coff);
    float4 s0 = s4[0], s1 = s4[1];
    float4 d0 = d4[0], d1 = d4[1];

    float ps = v0.x * s0.x + v0.y * s0.y + v0.z * s0.z + v0.w * s0.w
             + v1.x * s1.x + v1.y * s1.y + v1.z * s1.z + v1.w * s1.w;
    float pd = v0.x * d0.x + v0.y * d0.y + v0.z * d0.z + v0.w * d0.w
             + v1.x * d1.x + v1.y * d1.y + v1.z * d1.z + v1.w * d1.w;

#pragma unroll
    for (int o = 1; o < 8; o <<= 1) {
        ps += __shfl_xor_sync(0xFFFFFFFFu, ps, o);
        pd += __shfl_xor_sync(0xFFFFFFFFu, pd, o);
    }
    if ((lane & 7) == 0) {
        g_asrc[gwarp * HEADS + head] = ps;
        g_adst[gwarp * HEADS + head] = pd;
    }
}

// ---------------- K3: degree histogram -------------------------------------
__global__ void hist_kernel(const int* __restrict__ ei) {
    const int e = blockIdx.x * blockDim.x + threadIdx.x;
    if (e >= ETOT) return;
    const int d = (e < EE) ? ei[EE + e] : (e - EE);
    atomicAdd(g_deg + d, 1);
}

// ---------------- K4: exclusive scan -> row_ptr (single block) -------------
#define SCAN_T 1024
__global__ void scan_kernel() {
    __shared__ int ssum[SCAN_T];
    const int t = threadIdx.x;
    const int chunk = (NN + SCAN_T - 1) / SCAN_T;   // 49
    const int lo = t * chunk;
    const int hi = min(lo + chunk, NN);

    int s = 0;
    for (int i = lo; i < hi; i++) s += g_deg[i];
    ssum[t] = s;
    __syncthreads();

    for (int off = 1; off < SCAN_T; off <<= 1) {
        int v = (t >= off) ? ssum[t - off] : 0;
        __syncthreads();
        ssum[t] += v;
        __syncthreads();
    }

    int run = (t == 0) ? 0 : ssum[t - 1];
    for (int i = lo; i < hi; i++) {
        g_rowptr[i] = run;
        g_wp[i] = run;
        run += g_deg[i];
    }
    if (t == SCAN_T - 1) g_rowptr[NN] = ETOT;
}

// ---------------- K5: CSR fill (src ids grouped by dst) --------------------
__global__ void fill_kernel(const int* __restrict__ ei) {
    const int e = blockIdx.x * blockDim.x + threadIdx.x;
    if (e >= ETOT) return;
    int s, d;
    if (e < EE) { s = ei[e]; d = ei[EE + e]; }
    else        { s = d = e - EE; }
    const int pos = atomicAdd(g_wp + d, 1);
    g_csrc[pos] = s;
}

// ---------------- K6: warp-per-dst softmax + aggregate (fp16 gather) -------
__global__ void agg_kernel(const float* __restrict__ bias) {
    const int w    = (int)(((size_t)blockIdx.x * blockDim.x + threadIdx.x) >> 5);
    const int lane = threadIdx.x & 31;
    if (w >= NN) return;
    const int d  = w;
    const int e0 = g_rowptr[d];
    const int e1 = g_rowptr[d + 1];

    const float4 ad = *(const float4*)(g_adst + 4 * d);

    // ---- pass A: max logit per head ----
    float4 m = make_float4(-CUDART_INF_F, -CUDART_INF_F,
                           -CUDART_INF_F, -CUDART_INF_F);
    for (int e = e0 + lane; e < e1; e += 32) {
        const int s = g_csrc[e];
        const float4 as = *(const float4*)(g_asrc + 4 * s);
        m.x = fmaxf(m.x, lrelu(as.x + ad.x));
        m.y = fmaxf(m.y, lrelu(as.y + ad.y));
        m.z = fmaxf(m.z, lrelu(as.z + ad.z));
        m.w = fmaxf(m.w, lrelu(as.w + ad.w));
    }
#pragma unroll
    for (int o = 16; o >= 1; o >>= 1) {
        m.x = fmaxf(m.x, __shfl_xor_sync(0xFFFFFFFFu, m.x, o));
        m.y = fmaxf(m.y, __shfl_xor_sync(0xFFFFFFFFu, m.y, o));
        m.z = fmaxf(m.z, __shfl_xor_sync(0xFFFFFFFFu, m.z, o));
        m.w = fmaxf(m.w, __shfl_xor_sync(0xFFFFFFFFu, m.w, o));
    }

    // ---- pass B: exp-sum per head ----
    float4 sm = make_float4(0.f, 0.f, 0.f, 0.f);
    for (int e = e0 + lane; e < e1; e += 32) {
        const int s = g_csrc[e];
        const float4 as = *(const float4*)(g_asrc + 4 * s);
        sm.x += expf(lrelu(as.x + ad.x) - m.x);
        sm.y += expf(lrelu(as.y + ad.y) - m.y);
        sm.z += expf(lrelu(as.z + ad.z) - m.z);
        sm.w += expf(lrelu(as.w + ad.w) - m.w);
    }
#pragma unroll
    for (int o = 16; o >= 1; o >>= 1) {
        sm.x += __shfl_xor_sync(0xFFFFFFFFu, sm.x, o);
        sm.y += __shfl_xor_sync(0xFFFFFFFFu, sm.y, o);
        sm.z += __shfl_xor_sync(0xFFFFFFFFu, sm.z, o);
        sm.w += __shfl_xor_sync(0xFFFFFFFFu, sm.w, o);
    }

    // ---- per-lane head scalars ----
    const int head = lane >> 3;
    const float mh  = (head == 0) ? m.x : (head == 1) ? m.y
                    : (head == 2) ? m.z : m.w;
    const float shs = (head == 0) ? sm.x : (head == 1) ? sm.y
                    : (head == 2) ? sm.z : sm.w;
    const float adh = (head == 0) ? ad.x : (head == 1) ? ad.y
                    : (head == 2) ? ad.z : ad.w;
    const float inv = 1.f / (shs + 1e-16f);

    // ---- pass C: weighted fp16 gather-accumulate ----
    float a0 = 0.f, a1 = 0.f, a2 = 0.f, a3 = 0.f;
    float a4 = 0.f, a5 = 0.f, a6 = 0.f, a7 = 0.f;

    int s_cur = g_csrc[e0];               // e1 > e0 always (self-loop)
    for (int e = e0; e < e1; e++) {
        const int s_nxt = (e + 1 < e1) ? g_csrc[e + 1] : 0;  // prefetch
        const float4 as = *(const float4*)(g_asrc + 4 * s_cur);
        const float ash = (head == 0) ? as.x : (head == 1) ? as.y
                        : (head == 2) ? as.z : as.w;
        const float wgt = expf(lrelu(ash + adh) - mh) * inv;
        const uint4 hv = *(const uint4*)(g_xph + (size_t)s_cur * NHID + lane * 8);
        const __half2* hp = (const __half2*)&hv;
        const float2 f0 = __half22float2(hp[0]);
        const float2 f1 = __half22float2(hp[1]);
        const float2 f2 = __half22float2(hp[2]);
        const float2 f3 = __half22float2(hp[3]);
        a0 = fmaf(wgt, f0.x, a0);
        a1 = fmaf(wgt, f0.y, a1);
        a2 = fmaf(wgt, f1.x, a2);
        a3 = fmaf(wgt, f1.y, a3);
        a4 = fmaf(wgt, f2.x, a4);
        a5 = fmaf(wgt, f2.y, a5);
        a6 = fmaf(wgt, f3.x, a6);
        a7 = fmaf(wgt, f3.y, a7);
        s_cur = s_nxt;
    }

    // ---- bias + relu + store h ----
    const float4 b0 = *(const float4*)(bias + lane * 8);
    const float4 b1 = *(const float4*)(bias + lane * 8 + 4);
    float4 h0, h1;
    h0.x = fmaxf(a0 + b0.x, 0.f);
    h0.y = fmaxf(a1 + b0.y, 0.f);
    h0.z = fmaxf(a2 + b0.z, 0.f);
    h0.w = fmaxf(a3 + b0.w, 0.f);
    h1.x = fmaxf(a4 + b1.x, 0.f);
    h1.y = fmaxf(a5 + b1.y, 0.f);
    h1.z = fmaxf(a6 + b1.z, 0.f);
    h1.w = fmaxf(a7 + b1.w, 0.f);
    float4* op = (float4*)(g_acc + (size_t)d * NHID + lane * 8);
    op[0] = h0;
    op[1] = h1;
}

// ---------------- K7: per-graph max/mean pooling ---------------------------
#define POOL_NODES 256
__global__ void pool_kernel(const int* __restrict__ batch) {
    const int c  = threadIdx.x;               // channel 0..255
    const int n0 = blockIdx.x * POOL_NODES;
    const int n1 = min(n0 + POOL_NODES, NN);
    const int cnt_local = n1 - n0;

    __shared__ int sb[POOL_NODES];
    for (int i = threadIdx.x; i < cnt_local; i += blockDim.x)
        sb[i] = batch[n0 + i];
    __syncthreads();

    int curg = sb[0];
    float mx = 0.f, sm = 0.f;
    int cnt = 0;

    for (int i = 0; i < cnt_local; i++) {
        const int g = sb[i];
        if (g != curg) {
            atomicMax((int*)&g_pmax[curg * NHID + c], __float_as_int(mx));
            atomicAdd(&g_psum[curg * NHID + c], sm);
            if (c == 0) atomicAdd(&g_cnt[curg], cnt);
            curg = g; mx = 0.f; sm = 0.f; cnt = 0;
        }
        const float h = g_acc[(size_t)(n0 + i) * NHID + c];  // h >= 0
        mx = fmaxf(mx, h);
        sm += h;
        cnt++;
    }
    atomicMax((int*)&g_pmax[curg * NHID + c], __float_as_int(mx));
    atomicAdd(&g_psum[curg * NHID + c], sm);
    if (c == 0) atomicAdd(&g_cnt[curg], cnt);
}

// ---------------- K8: write output [NG, 2*NHID] ----------------------------
__global__ void final_kernel(float* __restrict__ out) {
    const int i = blockIdx.x * blockDim.x + threadIdx.x;
    if (i >= NG * NHID) return;
    const int g = i >> 8;
    const int c = i & 255;
    out[g * (2 * NHID) + c] = g_pmax[i];
    out[g * (2 * NHID) + NHID + c] = g_psum[i] / ((float)g_cnt[g] + 1e-16f);
}

// ---------------- launcher -------------------------------------------------
extern "C" void kernel_launch(void* const* d_in, const int* in_sizes, int n_in,
                              void* d_out, int out_size) {
    const float* x       = (const float*)d_in[0];
    const int*   ei      = (const int*)d_in[1];
    const int*   batch   = (const int*)d_in[2];
    const float* W       = (const float*)d_in[3];
    const float* att_src = (const float*)d_in[4];
    const float* att_dst = (const float*)d_in[5];
    const float* bias    = (const float*)d_in[6];
    float* out = (float*)d_out;

    zero_kernel<<<(NN + 255) / 256, 256>>>();
    {
        dim3 grid((NN + BM - 1) / BM, NHID / BN);
        gemm_kernel<<<grid, 256>>>(x, W);
    }
    acoef_kernel<<<(NN * 32 + 255) / 256, 256>>>(att_src, att_dst);
    hist_kernel<<<(ETOT + 255) / 256, 256>>>(ei);
    scan_kernel<<<1, SCAN_T>>>();
    fill_kernel<<<(ETOT + 255) / 256, 256>>>(ei);
    {
        long long total = (long long)NN * 32;
        agg_kernel<<<(int)((total + 255) / 256), 256>>>(bias);
    }
    pool_kernel<<<(NN + POOL_NODES - 1) / POOL_NODES, 256>>>(batch);
    final_kernel<<<(NG * NHID + 255) / 256, 256>>>(out);
}

// round 10
// speedup vs baseline: 1.3882x; 1.1080x over previous
#include <cuda_runtime.h>
#include <cuda_fp16.h>
#include <math_constants.h>

#define NN 50000
#define EE 800000
#define ETOT (EE + NN)
#define FIN 128
#define NHID 256
#define HEADS 4
#define CH 64
#define NG 16
#define NEG_SLOPE 0.2f

// ---------------- scratch (device globals; no allocation allowed) ----------
__device__ __half g_xph [(size_t)NN * NHID];   // x @ W (fp16)
__device__ float  g_acc [(size_t)NN * NHID];   // h = relu(agg + bias)
__device__ float  g_asrc[NN * HEADS];
__device__ float  g_adst[NN * HEADS];
__device__ int    g_deg [NN];
__device__ int    g_rowptr[NN + 1];
__device__ int    g_wp  [NN];
__device__ int    g_csrc[ETOT];
__device__ float  g_pmax[NG * NHID];
__device__ float  g_psum[NG * NHID];
__device__ int    g_cnt [NG];

// ---------------- helpers --------------------------------------------------
__device__ __forceinline__ float lrelu(float x) {
    return x > 0.f ? x : NEG_SLOPE * x;
}

// ---------------- K0: zero small scratch -----------------------------------
__global__ void zero_kernel() {
    int i = blockIdx.x * blockDim.x + threadIdx.x;
    if (i < NN) g_deg[i] = 0;
    if (i < NG * NHID) { g_pmax[i] = 0.f; g_psum[i] = 0.f; }
    if (i < NG) g_cnt[i] = 0;
}

// ---------------- K1: SGEMM  xph = fp16(x @ W)  ----------------------------
// 128x128 tile, BK=8, 256 threads, 8x8 microtile, double-buffered smem.
#define BM 128
#define BN 128
#define BK 8
#define ASPAD 132
__global__ void __launch_bounds__(256, 2)
gemm_kernel(const float* __restrict__ A, const float* __restrict__ B) {
    __shared__ float As[2][BK][ASPAD];
    __shared__ float Bs[2][BK][BN];

    const int tid = threadIdx.x;          // 0..255
    const int tx = tid & 15;
    const int ty = tid >> 4;
    const int bm = blockIdx.x * BM;
    const int bn = blockIdx.y * BN;

    const int arow  = tid >> 1;           // 0..127
    const int acol4 = (tid & 1) * 4;      // 0 or 4
    const int brow  = tid >> 5;           // 0..7
    const int bcol4 = (tid & 31) * 4;     // 0..124

    const int gm = bm + arow;
    const bool aok = (gm < NN);
    const float* aptr = A + (size_t)(aok ? gm : 0) * FIN + acol4;
    const float* bptr = B + (size_t)brow * NHID + bn + bcol4;

    float acc[8][8];
#pragma unroll
    for (int i = 0; i < 8; i++)
#pragma unroll
        for (int j = 0; j < 8; j++) acc[i][j] = 0.f;

    // preload tile 0
    float4 av = make_float4(0.f, 0.f, 0.f, 0.f);
    if (aok) av = *(const float4*)(aptr);
    float4 bv = *(const float4*)(bptr);
    As[0][acol4 + 0][arow] = av.x;
    As[0][acol4 + 1][arow] = av.y;
    As[0][acol4 + 2][arow] = av.z;
    As[0][acol4 + 3][arow] = av.w;
    *(float4*)&Bs[0][brow][bcol4] = bv;
    __syncthreads();

    const int NT = FIN / BK;   // 16
    int buf = 0;
#pragma unroll 4
    for (int t = 0; t < NT; t++) {
        if (t + 1 < NT) {
            av = make_float4(0.f, 0.f, 0.f, 0.f);
            if (aok) av = *(const float4*)(aptr + (t + 1) * BK);
            bv = *(const float4*)(bptr + (size_t)(t + 1) * BK * NHID);
        }
#pragma unroll
        for (int k = 0; k < BK; k++) {
            float af[8], bf[8];
            *(float4*)&af[0] = *(const float4*)&As[buf][k][ty * 8 + 0];
            *(float4*)&af[4] = *(const float4*)&As[buf][k][ty * 8 + 4];
            *(float4*)&bf[0] = *(const float4*)&Bs[buf][k][tx * 8 + 0];
            *(float4*)&bf[4] = *(const float4*)&Bs[buf][k][tx * 8 + 4];
#pragma unroll
            for (int i = 0; i < 8; i++)
#pragma unroll
                for (int j = 0; j < 8; j++)
                    acc[i][j] = fmaf(af[i], bf[j], acc[i][j]);
        }
        if (t + 1 < NT) {
            const int nb = buf ^ 1;
            As[nb][acol4 + 0][arow] = av.x;
            As[nb][acol4 + 1][arow] = av.y;
            As[nb][acol4 + 2][arow] = av.z;
            As[nb][acol4 + 3][arow] = av.w;
            *(float4*)&Bs[nb][brow][bcol4] = bv;
            __syncthreads();
            buf = nb;
        }
    }

#pragma unroll
    for (int i = 0; i < 8; i++) {
        const int gr = bm + ty * 8 + i;
        if (gr < NN) {
            __half2 h[4];
            h[0] = __floats2half2_rn(acc[i][0], acc[i][1]);
            h[1] = __floats2half2_rn(acc[i][2], acc[i][3]);
            h[2] = __floats2half2_rn(acc[i][4], acc[i][5]);
            h[3] = __floats2half2_rn(acc[i][6], acc[i][7]);
            *(uint4*)(g_xph + (size_t)gr * NHID + bn + tx * 8) = *(uint4*)h;
        }
    }
}

// ---------------- K2: attention coefficients from fp16 xp ------------------
__global__ void acoef_kernel(const float* __restrict__ att_src,
                             const float* __restrict__ att_dst) {
    const int gwarp = (blockIdx.x * blockDim.x + threadIdx.x) >> 5;
    const int lane  = threadIdx.x & 31;
    if (gwarp >= NN) return;

    const uint4 hv = *(const uint4*)(g_xph + (size_t)gwarp * NHID + lane * 8);
    const __half2* hp = (const __half2*)&hv;
    const float2 f0 = __half22float2(hp[0]);
    const float2 f1 = __half22float2(hp[1]);
    const float2 f2 = __half22float2(hp[2]);
    const float2 f3 = __half22float2(hp[3]);

    const int head = lane >> 3;
    const int coff = (lane & 7) * 8;
    const float4* s4 = (const float4*)(att_src + head * CH + coff);
    const float4* d4 = (const float4*)(att_dst + head * CH + coff);
    const float4 s0 = s4[0], s1 = s4[1];
    const float4 d0 = d4[0], d1 = d4[1];

    float ps = f0.x * s0.x + f0.y * s0.y + f1.x * s0.z + f1.y * s0.w
             + f2.x * s1.x + f2.y * s1.y + f3.x * s1.z + f3.y * s1.w;
    float pd = f0.x * d0.x + f0.y * d0.y + f1.x * d0.z + f1.y * d0.w
             + f2.x * d1.x + f2.y * d1.y + f3.x * d1.z + f3.y * d1.w;

#pragma unroll
    for (int o = 1; o < 8; o <<= 1) {
        ps += __shfl_xor_sync(0xFFFFFFFFu, ps, o);
        pd += __shfl_xor_sync(0xFFFFFFFFu, pd, o);
    }
    if ((lane & 7) == 0) {
        g_asrc[gwarp * HEADS + head] = ps;
        g_adst[gwarp * HEADS + head] = pd;
    }
}

// ---------------- K3: degree histogram -------------------------------------
__global__ void hist_kernel(const int* __restrict__ ei) {
    const int e = blockIdx.x * blockDim.x + threadIdx.x;
    if (e >= ETOT) return;
    const int d = (e < EE) ? ei[EE + e] : (e - EE);
    atomicAdd(g_deg + d, 1);
}

// ---------------- K4: exclusive scan -> row_ptr (single block) -------------
#define SCAN_T 1024
__global__ void scan_kernel() {
    __shared__ int ssum[SCAN_T];
    const int t = threadIdx.x;
    const int chunk = (NN + SCAN_T - 1) / SCAN_T;   // 49
    const int lo = t * chunk;
    const int hi = min(lo + chunk, NN);

    int s = 0;
    for (int i = lo; i < hi; i++) s += g_deg[i];
    ssum[t] = s;
    __syncthreads();

    for (int off = 1; off < SCAN_T; off <<= 1) {
        int v = (t >= off) ? ssum[t - off] : 0;
        __syncthreads();
        ssum[t] += v;
        __syncthreads();
    }

    int run = (t == 0) ? 0 : ssum[t - 1];
    for (int i = lo; i < hi; i++) {
        g_rowptr[i] = run;
        g_wp[i] = run;
        run += g_deg[i];
    }
    if (t == SCAN_T - 1) g_rowptr[NN] = ETOT;
}

// ---------------- K5: CSR fill (src ids grouped by dst) --------------------
__global__ void fill_kernel(const int* __restrict__ ei) {
    const int e = blockIdx.x * blockDim.x + threadIdx.x;
    if (e >= ETOT) return;
    int s, d;
    if (e < EE) { s = ei[e]; d = ei[EE + e]; }
    else        { s = d = e - EE; }
    const int pos = atomicAdd(g_wp + d, 1);
    g_csrc[pos] = s;
}

// ---------------- K6: warp-per-dst online softmax + pipelined gather -------
__global__ void agg_kernel(const float* __restrict__ bias) {
    const int w    = (int)(((size_t)blockIdx.x * blockDim.x + threadIdx.x) >> 5);
    const int lane = threadIdx.x & 31;
    if (w >= NN) return;
    const int d  = w;
    const int e0 = g_rowptr[d];
    const int e1 = g_rowptr[d + 1];

    const float4 ad = *(const float4*)(g_adst + 4 * d);

    // ---- merged pass A+B: online (max, exp-sum) per head, lane-strided ----
    float4 m = make_float4(-1e30f, -1e30f, -1e30f, -1e30f);
    float4 sm = make_float4(0.f, 0.f, 0.f, 0.f);
    for (int e = e0 + lane; e < e1; e += 32) {
        const int s = g_csrc[e];
        const float4 as = *(const float4*)(g_asrc + 4 * s);
        float l;
        l = lrelu(as.x + ad.x);
        if (l > m.x) { sm.x = sm.x * __expf(m.x - l) + 1.f; m.x = l; }
        else         { sm.x += __expf(l - m.x); }
        l = lrelu(as.y + ad.y);
        if (l > m.y) { sm.y = sm.y * __expf(m.y - l) + 1.f; m.y = l; }
        else         { sm.y += __expf(l - m.y); }
        l = lrelu(as.z + ad.z);
        if (l > m.z) { sm.z = sm.z * __expf(m.z - l) + 1.f; m.z = l; }
        else         { sm.z += __expf(l - m.z); }
        l = lrelu(as.w + ad.w);
        if (l > m.w) { sm.w = sm.w * __expf(m.w - l) + 1.f; m.w = l; }
        else         { sm.w += __expf(l - m.w); }
    }
    // warp merge of (m, s)
#pragma unroll
    for (int o = 16; o >= 1; o >>= 1) {
        float mo, so, nm;
        mo = __shfl_xor_sync(0xFFFFFFFFu, m.x, o);
        so = __shfl_xor_sync(0xFFFFFFFFu, sm.x, o);
        nm = fmaxf(m.x, mo);
        sm.x = sm.x * __expf(m.x - nm) + so * __expf(mo - nm);
        m.x = nm;
        mo = __shfl_xor_sync(0xFFFFFFFFu, m.y, o);
        so = __shfl_xor_sync(0xFFFFFFFFu, sm.y, o);
        nm = fmaxf(m.y, mo);
        sm.y = sm.y * __expf(m.y - nm) + so * __expf(mo - nm);
        m.y = nm;
        mo = __shfl_xor_sync(0xFFFFFFFFu, m.z, o);
        so = __shfl_xor_sync(0xFFFFFFFFu, sm.z, o);
        nm = fmaxf(m.z, mo);
        sm.z = sm.z * __expf(m.z - nm) + so * __expf(mo - nm);
        m.z = nm;
        mo = __shfl_xor_sync(0xFFFFFFFFu, m.w, o);
        so = __shfl_xor_sync(0xFFFFFFFFu, sm.w, o);
        nm = fmaxf(m.w, mo);
        sm.w = sm.w * __expf(m.w - nm) + so * __expf(mo - nm);
        m.w = nm;
    }

    // ---- per-lane head scalars ----
    const int head = lane >> 3;
    const float mh  = (head == 0) ? m.x : (head == 1) ? m.y
                    : (head == 2) ? m.z : m.w;
    const float shs = (head == 0) ? sm.x : (head == 1) ? sm.y
                    : (head == 2) ? sm.z : sm.w;
    const float adh = (head == 0) ? ad.x : (head == 1) ? ad.y
                    : (head == 2) ? ad.z : ad.w;
    const float inv = 1.f / (shs + 1e-16f);

    // ---- pass C: software-pipelined weighted fp16 gather ----
    float a0 = 0.f, a1 = 0.f, a2 = 0.f, a3 = 0.f;
    float a4 = 0.f, a5 = 0.f, a6 = 0.f, a7 = 0.f;

    int s_cur = g_csrc[e0];               // e1 > e0 always (self-loop)
    uint4 hv = *(const uint4*)(g_xph + (size_t)s_cur * NHID + lane * 8);
    float ash = g_asrc[4 * s_cur + head];

    for (int e = e0; e < e1; e++) {
        const int s_nxt = (e + 1 < e1) ? g_csrc[e + 1] : s_cur;
        const uint4 hv_nxt =
            *(const uint4*)(g_xph + (size_t)s_nxt * NHID + lane * 8);
        const float ash_nxt = g_asrc[4 * s_nxt + head];

        const float wgt = __expf(lrelu(ash + adh) - mh) * inv;
        const __half2* hp = (const __half2*)&hv;
        const float2 f0 = __half22float2(hp[0]);
        const float2 f1 = __half22float2(hp[1]);
        const float2 f2 = __half22float2(hp[2]);
        const float2 f3 = __half22float2(hp[3]);
        a0 = fmaf(wgt, f0.x, a0);
        a1 = fmaf(wgt, f0.y, a1);
        a2 = fmaf(wgt, f1.x, a2);
        a3 = fmaf(wgt, f1.y, a3);
        a4 = fmaf(wgt, f2.x, a4);
        a5 = fmaf(wgt, f2.y, a5);
        a6 = fmaf(wgt, f3.x, a6);
        a7 = fmaf(wgt, f3.y, a7);

        hv = hv_nxt;
        ash = ash_nxt;
        s_cur = s_nxt;
    }

    // ---- bias + relu + store h ----
    const float4 b0 = *(const float4*)(bias + lane * 8);
    const float4 b1 = *(const float4*)(bias + lane * 8 + 4);
    float4 h0, h1;
    h0.x = fmaxf(a0 + b0.x, 0.f);
    h0.y = fmaxf(a1 + b0.y, 0.f);
    h0.z = fmaxf(a2 + b0.z, 0.f);
    h0.w = fmaxf(a3 + b0.w, 0.f);
    h1.x = fmaxf(a4 + b1.x, 0.f);
    h1.y = fmaxf(a5 + b1.y, 0.f);
    h1.z = fmaxf(a6 + b1.z, 0.f);
    h1.w = fmaxf(a7 + b1.w, 0.f);
    float4* op = (float4*)(g_acc + (size_t)d * NHID + lane * 8);
    op[0] = h0;
    op[1] = h1;
}

// ---------------- K7: per-graph max/mean pooling ---------------------------
#define POOL_NODES 256
__global__ void pool_kernel(const int* __restrict__ batch) {
    const int c  = threadIdx.x;               // channel 0..255
    const int n0 = blockIdx.x * POOL_NODES;
    const int n1 = min(n0 + POOL_NODES, NN);
    const int cnt_local = n1 - n0;

    __shared__ int sb[POOL_NODES];
    for (int i = threadIdx.x; i < cnt_local; i += blockDim.x)
        sb[i] = batch[n0 + i];
    __syncthreads();

    int curg = sb[0];
    float mx = 0.f, sm = 0.f;
    int cnt = 0;

    for (int i = 0; i < cnt_local; i++) {
        const int g = sb[i];
        if (g != curg) {
            atomicMax((int*)&g_pmax[curg * NHID + c], __float_as_int(mx));
            atomicAdd(&g_psum[curg * NHID + c], sm);
            if (c == 0) atomicAdd(&g_cnt[curg], cnt);
            curg = g; mx = 0.f; sm = 0.f; cnt = 0;
        }
        const float h = g_acc[(size_t)(n0 + i) * NHID + c];  // h >= 0
        mx = fmaxf(mx, h);
        sm += h;
        cnt++;
    }
    atomicMax((int*)&g_pmax[curg * NHID + c], __float_as_int(mx));
    atomicAdd(&g_psum[curg * NHID + c], sm);
    if (c == 0) atomicAdd(&g_cnt[curg], cnt);
}

// ---------------- K8: write output [NG, 2*NHID] ----------------------------
__global__ void final_kernel(float* __restrict__ out) {
    const int i = blockIdx.x * blockDim.x + threadIdx.x;
    if (i >= NG * NHID) return;
    const int g = i >> 8;
    const int c = i & 255;
    out[g * (2 * NHID) + c] = g_pmax[i];
    out[g * (2 * NHID) + NHID + c] = g_psum[i] / ((float)g_cnt[g] + 1e-16f);
}

// ---------------- launcher -------------------------------------------------
extern "C" void kernel_launch(void* const* d_in, const int* in_sizes, int n_in,
                              void* d_out, int out_size) {
    const float* x       = (const float*)d_in[0];
    const int*   ei      = (const int*)d_in[1];
    const int*   batch   = (const int*)d_in[2];
    const float* W       = (const float*)d_in[3];
    const float* att_src = (const float*)d_in[4];
    const float* att_dst = (const float*)d_in[5];
    const float* bias    = (const float*)d_in[6];
    float* out = (float*)d_out;

    zero_kernel<<<(NN + 255) / 256, 256>>>();
    {
        dim3 grid((NN + BM - 1) / BM, NHID / BN);
        gemm_kernel<<<grid, 256>>>(x, W);
    }
    acoef_kernel<<<(NN * 32 + 255) / 256, 256>>>(att_src, att_dst);
    hist_kernel<<<(ETOT + 255) / 256, 256>>>(ei);
    scan_kernel<<<1, SCAN_T>>>();
    fill_kernel<<<(ETOT + 255) / 256, 256>>>(ei);
    {
        long long total = (long long)NN * 32;
        agg_kernel<<<(int)((total + 255) / 256), 256>>>(bias);
    }
    pool_kernel<<<(NN + POOL_NODES - 1) / POOL_NODES, 256>>>(batch);
    final_kernel<<<(NG * NHID + 255) / 256, 256>>>(out);
}

// round 12
// speedup vs baseline: 1.4286x; 1.0291x over previous
#include <cuda_runtime.h>
#include <cuda_fp16.h>
#include <math_constants.h>

#define NN 50000
#define EE 800000
#define ETOT (EE + NN)
#define FIN 128
#define NHID 256
#define HEADS 4
#define CH 64
#define NG 16
#define NEG_SLOPE 0.2f

// ---------------- scratch (device globals; no allocation allowed) ----------
__device__ __half g_xph [(size_t)NN * NHID];   // x @ W (fp16)
__device__ float  g_acc [(size_t)NN * NHID];   // h = relu(agg + bias)
__device__ float  g_asrc[NN * HEADS];
__device__ float  g_adst[NN * HEADS];
__device__ int    g_deg [NN];
__device__ int    g_rowptr[NN + 1];
__device__ int    g_wp  [NN];
__device__ int    g_csrc[ETOT];
__device__ float  g_pmax[NG * NHID];
__device__ float  g_psum[NG * NHID];
__device__ int    g_cnt [NG];

// ---------------- helpers --------------------------------------------------
__device__ __forceinline__ float lrelu(float x) {
    return x > 0.f ? x : NEG_SLOPE * x;
}

// ---------------- K0: zero small scratch -----------------------------------
__global__ void zero_kernel() {
    int i = blockIdx.x * blockDim.x + threadIdx.x;
    if (i < NN) g_deg[i] = 0;
    if (i < NG * NHID) { g_pmax[i] = 0.f; g_psum[i] = 0.f; }
    if (i < NG) g_cnt[i] = 0;
}

// ---------------- K1: SGEMM  xph = fp16(x @ W)  ----------------------------
// 128x128 tile, BK=8, 256 threads, 8x8 microtile, double-buffered smem.
#define BM 128
#define BN 128
#define BK 8
#define ASPAD 132
__global__ void __launch_bounds__(256, 2)
gemm_kernel(const float* __restrict__ A, const float* __restrict__ B) {
    __shared__ float As[2][BK][ASPAD];
    __shared__ float Bs[2][BK][BN];

    const int tid = threadIdx.x;          // 0..255
    const int tx = tid & 15;
    const int ty = tid >> 4;
    const int bm = blockIdx.x * BM;
    const int bn = blockIdx.y * BN;

    const int arow  = tid >> 1;           // 0..127
    const int acol4 = (tid & 1) * 4;      // 0 or 4
    const int brow  = tid >> 5;           // 0..7
    const int bcol4 = (tid & 31) * 4;     // 0..124

    const int gm = bm + arow;
    const bool aok = (gm < NN);
    const float* aptr = A + (size_t)(aok ? gm : 0) * FIN + acol4;
    const float* bptr = B + (size_t)brow * NHID + bn + bcol4;

    float acc[8][8];
#pragma unroll
    for (int i = 0; i < 8; i++)
#pragma unroll
        for (int j = 0; j < 8; j++) acc[i][j] = 0.f;

    // preload tile 0
    float4 av = make_float4(0.f, 0.f, 0.f, 0.f);
    if (aok) av = *(const float4*)(aptr);
    float4 bv = *(const float4*)(bptr);
    As[0][acol4 + 0][arow] = av.x;
    As[0][acol4 + 1][arow] = av.y;
    As[0][acol4 + 2][arow] = av.z;
    As[0][acol4 + 3][arow] = av.w;
    *(float4*)&Bs[0][brow][bcol4] = bv;
    __syncthreads();

    const int NT = FIN / BK;   // 16
    int buf = 0;
#pragma unroll 4
    for (int t = 0; t < NT; t++) {
        if (t + 1 < NT) {
            av = make_float4(0.f, 0.f, 0.f, 0.f);
            if (aok) av = *(const float4*)(aptr + (t + 1) * BK);
            bv = *(const float4*)(bptr + (size_t)(t + 1) * BK * NHID);
        }
#pragma unroll
        for (int k = 0; k < BK; k++) {
            float af[8], bf[8];
            *(float4*)&af[0] = *(const float4*)&As[buf][k][ty * 8 + 0];
            *(float4*)&af[4] = *(const float4*)&As[buf][k][ty * 8 + 4];
            *(float4*)&bf[0] = *(const float4*)&Bs[buf][k][tx * 8 + 0];
            *(float4*)&bf[4] = *(const float4*)&Bs[buf][k][tx * 8 + 4];
#pragma unroll
            for (int i = 0; i < 8; i++)
#pragma unroll
                for (int j = 0; j < 8; j++)
                    acc[i][j] = fmaf(af[i], bf[j], acc[i][j]);
        }
        if (t + 1 < NT) {
            const int nb = buf ^ 1;
            As[nb][acol4 + 0][arow] = av.x;
            As[nb][acol4 + 1][arow] = av.y;
            As[nb][acol4 + 2][arow] = av.z;
            As[nb][acol4 + 3][arow] = av.w;
            *(float4*)&Bs[nb][brow][bcol4] = bv;
            __syncthreads();
            buf = nb;
        }
    }

#pragma unroll
    for (int i = 0; i < 8; i++) {
        const int gr = bm + ty * 8 + i;
        if (gr < NN) {
            __half2 h[4];
            h[0] = __floats2half2_rn(acc[i][0], acc[i][1]);
            h[1] = __floats2half2_rn(acc[i][2], acc[i][3]);
            h[2] = __floats2half2_rn(acc[i][4], acc[i][5]);
            h[3] = __floats2half2_rn(acc[i][6], acc[i][7]);
            *(uint4*)(g_xph + (size_t)gr * NHID + bn + tx * 8) = *(uint4*)h;
        }
    }
}

// ---------------- K2: attention coefficients from fp16 xp ------------------
__global__ void acoef_kernel(const float* __restrict__ att_src,
                             const float* __restrict__ att_dst) {
    const int gwarp = (blockIdx.x * blockDim.x + threadIdx.x) >> 5;
    const int lane  = threadIdx.x & 31;
    if (gwarp >= NN) return;

    const uint4 hv = *(const uint4*)(g_xph + (size_t)gwarp * NHID + lane * 8);
    const __half2* hp = (const __half2*)&hv;
    const float2 f0 = __half22float2(hp[0]);
    const float2 f1 = __half22float2(hp[1]);
    const float2 f2 = __half22float2(hp[2]);
    const float2 f3 = __half22float2(hp[3]);

    const int head = lane >> 3;
    const int coff = (lane & 7) * 8;
    const float4* s4 = (const float4*)(att_src + head * CH + coff);
    const float4* d4 = (const float4*)(att_dst + head * CH + coff);
    const float4 s0 = s4[0], s1 = s4[1];
    const float4 d0 = d4[0], d1 = d4[1];

    float ps = f0.x * s0.x + f0.y * s0.y + f1.x * s0.z + f1.y * s0.w
             + f2.x * s1.x + f2.y * s1.y + f3.x * s1.z + f3.y * s1.w;
    float pd = f0.x * d0.x + f0.y * d0.y + f1.x * d0.z + f1.y * d0.w
             + f2.x * d1.x + f2.y * d1.y + f3.x * d1.z + f3.y * d1.w;

#pragma unroll
    for (int o = 1; o < 8; o <<= 1) {
        ps += __shfl_xor_sync(0xFFFFFFFFu, ps, o);
        pd += __shfl_xor_sync(0xFFFFFFFFu, pd, o);
    }
    if ((lane & 7) == 0) {
        g_asrc[gwarp * HEADS + head] = ps;
        g_adst[gwarp * HEADS + head] = pd;
    }
}

// ---------------- K3: degree histogram -------------------------------------
__global__ void hist_kernel(const int* __restrict__ ei) {
    const int e = blockIdx.x * blockDim.x + threadIdx.x;
    if (e >= ETOT) return;
    const int d = (e < EE) ? ei[EE + e] : (e - EE);
    atomicAdd(g_deg + d, 1);
}

// ---------------- K4: exclusive scan -> row_ptr (single block) -------------
#define SCAN_T 1024
__global__ void scan_kernel() {
    __shared__ int ssum[SCAN_T];
    const int t = threadIdx.x;
    const int chunk = (NN + SCAN_T - 1) / SCAN_T;   // 49
    const int lo = t * chunk;
    const int hi = min(lo + chunk, NN);

    int s = 0;
    for (int i = lo; i < hi; i++) s += g_deg[i];
    ssum[t] = s;
    __syncthreads();

    for (int off = 1; off < SCAN_T; off <<= 1) {
        int v = (t >= off) ? ssum[t - off] : 0;
        __syncthreads();
        ssum[t] += v;
        __syncthreads();
    }

    int run = (t == 0) ? 0 : ssum[t - 1];
    for (int i = lo; i < hi; i++) {
        g_rowptr[i] = run;
        g_wp[i] = run;
        run += g_deg[i];
    }
    if (t == SCAN_T - 1) g_rowptr[NN] = ETOT;
}

// ---------------- K5: CSR fill (src ids grouped by dst) --------------------
__global__ void fill_kernel(const int* __restrict__ ei) {
    const int e = blockIdx.x * blockDim.x + threadIdx.x;
    if (e >= ETOT) return;
    int s, d;
    if (e < EE) { s = ei[e]; d = ei[EE + e]; }
    else        { s = d = e - EE; }
    const int pos = atomicAdd(g_wp + d, 1);
    g_csrc[pos] = s;
}

// ---------------- K6: warp-per-dst SINGLE-PASS online softmax-aggregate ----
// Each lane owns 8 channels and walks every incoming edge, maintaining its
// own (m, s) online-softmax state (identical across lanes of a head — no
// shuffles needed). Unroll-by-2 with prefetch distance 2 for MLP=4.
__global__ void agg_kernel(const float* __restrict__ bias) {
    const int w    = (int)(((size_t)blockIdx.x * blockDim.x + threadIdx.x) >> 5);
    const int lane = threadIdx.x & 31;
    if (w >= NN) return;
    const int d   = w;
    const int e0  = g_rowptr[d];
    const int cnt = g_rowptr[d + 1] - e0;   // >= 1 (self-loop)

    const int head  = lane >> 3;
    const float adh = g_adst[4 * d + head];
    const __half* xb = g_xph + (size_t)lane * 8;

    float m = -1e30f, s = 0.f;
    float a0 = 0.f, a1 = 0.f, a2 = 0.f, a3 = 0.f;
    float a4 = 0.f, a5 = 0.f, a6 = 0.f, a7 = 0.f;

#define AGG_PROC(HV, XV) do {                                               \
        const float l_ = lrelu((XV) + adh);                                  \
        float wgt_;                                                          \
        if (l_ > m) {                                                        \
            const float sc_ = __expf(m - l_);                                \
            s = s * sc_ + 1.f;                                               \
            a0 *= sc_; a1 *= sc_; a2 *= sc_; a3 *= sc_;                      \
            a4 *= sc_; a5 *= sc_; a6 *= sc_; a7 *= sc_;                      \
            m = l_; wgt_ = 1.f;                                              \
        } else {                                                             \
            wgt_ = __expf(l_ - m); s += wgt_;                                \
        }                                                                    \
        const __half2* hp_ = (const __half2*)&(HV);                          \
        const float2 f0_ = __half22float2(hp_[0]);                           \
        const float2 f1_ = __half22float2(hp_[1]);                           \
        const float2 f2_ = __half22float2(hp_[2]);                           \
        const float2 f3_ = __half22float2(hp_[3]);                           \
        a0 = fmaf(wgt_, f0_.x, a0); a1 = fmaf(wgt_, f0_.y, a1);              \
        a2 = fmaf(wgt_, f1_.x, a2); a3 = fmaf(wgt_, f1_.y, a3);              \
        a4 = fmaf(wgt_, f2_.x, a4); a5 = fmaf(wgt_, f2_.y, a5);              \
        a6 = fmaf(wgt_, f3_.x, a6); a7 = fmaf(wgt_, f3_.y, a7);              \
    } while (0)

    // pipeline slots A (even i) and B (odd i), prefetch distance 2
    int sA = g_csrc[e0];
    uint4 hA = *(const uint4*)(xb + (size_t)sA * NHID);
    float xA = g_asrc[4 * sA + head];
    uint4 hB; float xB;
    if (cnt > 1) {
        const int sB = g_csrc[e0 + 1];
        hB = *(const uint4*)(xb + (size_t)sB * NHID);
        xB = g_asrc[4 * sB + head];
    }

    int i = 0;
    for (; i + 1 < cnt; i += 2) {
        // prefetch i+2, i+3 (clamped; redundant loads at tail are harmless)
        const int i2 = (i + 2 < cnt) ? (i + 2) : (cnt - 1);
        const int i3 = (i + 3 < cnt) ? (i + 3) : (cnt - 1);
        const int s2 = g_csrc[e0 + i2];
        const int s3 = g_csrc[e0 + i3];
        const uint4 h2 = *(const uint4*)(xb + (size_t)s2 * NHID);
        const uint4 h3 = *(const uint4*)(xb + (size_t)s3 * NHID);
        const float x2 = g_asrc[4 * s2 + head];
        const float x3 = g_asrc[4 * s3 + head];

        AGG_PROC(hA, xA);
        AGG_PROC(hB, xB);

        hA = h2; xA = x2;
        hB = h3; xB = x3;
    }
    if (i < cnt) AGG_PROC(hA, xA);
#undef AGG_PROC

    // ---- normalize + bias + relu + store h ----
    const float inv = 1.f / (s + 1e-16f);
    const float4 b0 = *(const float4*)(bias + lane * 8);
    const float4 b1 = *(const float4*)(bias + lane * 8 + 4);
    float4 h0, h1;
    h0.x = fmaxf(fmaf(a0, inv, b0.x), 0.f);
    h0.y = fmaxf(fmaf(a1, inv, b0.y), 0.f);
    h0.z = fmaxf(fmaf(a2, inv, b0.z), 0.f);
    h0.w = fmaxf(fmaf(a3, inv, b0.w), 0.f);
    h1.x = fmaxf(fmaf(a4, inv, b1.x), 0.f);
    h1.y = fmaxf(fmaf(a5, inv, b1.y), 0.f);
    h1.z = fmaxf(fmaf(a6, inv, b1.z), 0.f);
    h1.w = fmaxf(fmaf(a7, inv, b1.w), 0.f);
    float4* op = (float4*)(g_acc + (size_t)d * NHID + lane * 8);
    op[0] = h0;
    op[1] = h1;
}

// ---------------- K7: per-graph max/mean pooling ---------------------------
#define POOL_NODES 256
__global__ void pool_kernel(const int* __restrict__ batch) {
    const int c  = threadIdx.x;               // channel 0..255
    const int n0 = blockIdx.x * POOL_NODES;
    const int n1 = min(n0 + POOL_NODES, NN);
    const int cnt_local = n1 - n0;

    __shared__ int sb[POOL_NODES];
    for (int i = threadIdx.x; i < cnt_local; i += blockDim.x)
        sb[i] = batch[n0 + i];
    __syncthreads();

    int curg = sb[0];
    float mx = 0.f, sm = 0.f;
    int cnt = 0;

    for (int i = 0; i < cnt_local; i++) {
        const int g = sb[i];
        if (g != curg) {
            atomicMax((int*)&g_pmax[curg * NHID + c], __float_as_int(mx));
            atomicAdd(&g_psum[curg * NHID + c], sm);
            if (c == 0) atomicAdd(&g_cnt[curg], cnt);
            curg = g; mx = 0.f; sm = 0.f; cnt = 0;
        }
        const float h = g_acc[(size_t)(n0 + i) * NHID + c];  // h >= 0
        mx = fmaxf(mx, h);
        sm += h;
        cnt++;
    }
    atomicMax((int*)&g_pmax[curg * NHID + c], __float_as_int(mx));
    atomicAdd(&g_psum[curg * NHID + c], sm);
    if (c == 0) atomicAdd(&g_cnt[curg], cnt);
}

// ---------------- K8: write output [NG, 2*NHID] ----------------------------
__global__ void final_kernel(float* __restrict__ out) {
    const int i = blockIdx.x * blockDim.x + threadIdx.x;
    if (i >= NG * NHID) return;
    const int g = i >> 8;
    const int c = i & 255;
    out[g * (2 * NHID) + c] = g_pmax[i];
    out[g * (2 * NHID) + NHID + c] = g_psum[i] / ((float)g_cnt[g] + 1e-16f);
}

// ---------------- launcher -------------------------------------------------
extern "C" void kernel_launch(void* const* d_in, const int* in_sizes, int n_in,
                              void* d_out, int out_size) {
    const float* x       = (const float*)d_in[0];
    const int*   ei      = (const int*)d_in[1];
    const int*   batch   = (const int*)d_in[2];
    const float* W       = (const float*)d_in[3];
    const float* att_src = (const float*)d_in[4];
    const float* att_dst = (const float*)d_in[5];
    const float* bias    = (const float*)d_in[6];
    float* out = (float*)d_out;

    zero_kernel<<<(NN + 255) / 256, 256>>>();
    {
        dim3 grid((NN + BM - 1) / BM, NHID / BN);
        gemm_kernel<<<grid, 256>>>(x, W);
    }
    acoef_kernel<<<(NN * 32 + 255) / 256, 256>>>(att_src, att_dst);
    hist_kernel<<<(ETOT + 255) / 256, 256>>>(ei);
    scan_kernel<<<1, SCAN_T>>>();
    fill_kernel<<<(ETOT + 255) / 256, 256>>>(ei);
    {
        long long total = (long long)NN * 32;
        agg_kernel<<<(int)((total + 255) / 256), 256>>>(bias);
    }
    pool_kernel<<<(NN + POOL_NODES - 1) / POOL_NODES, 256>>>(batch);
    final_kernel<<<(NG * NHID + 255) / 256, 256>>>(out);
}

// round 13
// speedup vs baseline: 1.5398x; 1.0779x over previous
#include <cuda_runtime.h>
#include <cuda_fp16.h>
#include <math_constants.h>
#include <mma.h>

using namespace nvcuda;

#define NN 50000
#define EE 800000
#define ETOT (EE + NN)
#define FIN 128
#define NHID 256
#define HEADS 4
#define CH 64
#define NG 16
#define NEG_SLOPE 0.2f

// ---------------- scratch (device globals; no allocation allowed) ----------
__device__ __half g_xph [(size_t)NN * NHID];   // x @ W (fp16)
__device__ float  g_acc [(size_t)NN * NHID];   // h = relu(agg + bias)
__device__ float  g_asrc[NN * HEADS];
__device__ float  g_adst[NN * HEADS];
__device__ int    g_deg [NN];
__device__ int    g_rowptr[NN + 1];
__device__ int    g_wp  [NN];
__device__ int    g_csrc[ETOT];
__device__ float  g_pmax[NG * NHID];
__device__ float  g_psum[NG * NHID];
__device__ int    g_cnt [NG];

// ---------------- helpers --------------------------------------------------
__device__ __forceinline__ float lrelu(float x) {
    return x > 0.f ? x : NEG_SLOPE * x;
}

// ---------------- K0: zero small scratch -----------------------------------
__global__ void zero_kernel() {
    int i = blockIdx.x * blockDim.x + threadIdx.x;
    if (i < NN) g_deg[i] = 0;
    if (i < NG * NHID) { g_pmax[i] = 0.f; g_psum[i] = 0.f; }
    if (i < NG) g_cnt[i] = 0;
}

// ---------------- K1: tensor-core GEMM  xph = fp16(x @ W) ------------------
// Block tile 128x128, K-chunks of 64, 8 warps (4x2), warp tile 32x64.
// fp32 inputs converted to fp16 while staging into smem; HMMA via wmma;
// epilogue stages fp32 acc through per-warp smem in two 32-col phases.
#define GM_TILE 128
#define GN_TILE 128
#define GK_CHUNK 64
#define A_LD 72      // 64 + 8 halves
#define B_LD 136     // 128 + 8 halves
#define EPI_LD 36    // 32 + 4 floats
#define GEMM_SMEM 36864

__global__ void __launch_bounds__(256, 2)
gemm_kernel(const float* __restrict__ A, const float* __restrict__ B) {
    extern __shared__ unsigned char smem_raw[];
    __half* As = (__half*)smem_raw;                        // [128][A_LD]
    __half* Bs = (__half*)(smem_raw + 128 * A_LD * 2);     // [64][B_LD]

    const int tid  = threadIdx.x;
    const int wid  = tid >> 5;
    const int lane = tid & 31;
    const int warp_m = wid >> 1;       // 0..3
    const int warp_n = wid & 1;        // 0..1
    const int bm = blockIdx.x * GM_TILE;
    const int bn = blockIdx.y * GN_TILE;

    wmma::fragment<wmma::accumulator, 16, 16, 16, float> acc[2][4];
#pragma unroll
    for (int i = 0; i < 2; i++)
#pragma unroll
        for (int j = 0; j < 4; j++) wmma::fill_fragment(acc[i][j], 0.f);

    for (int k0 = 0; k0 < FIN; k0 += GK_CHUNK) {
        // ---- stage A chunk: 128 rows x 64 cols, fp32 -> fp16 ----
        {
            const int row   = tid >> 1;          // 0..127
            const int cbase = (tid & 1) * 32;    // 0 or 32
            const int gr = bm + row;
            __half* dst = As + row * A_LD + cbase;
            if (gr < NN) {
                const float* src = A + (size_t)gr * FIN + k0 + cbase;
#pragma unroll
                for (int c = 0; c < 32; c += 4) {
                    const float4 v = *(const float4*)(src + c);
                    *(__half2*)(dst + c + 0) = __floats2half2_rn(v.x, v.y);
                    *(__half2*)(dst + c + 2) = __floats2half2_rn(v.z, v.w);
                }
            } else {
#pragma unroll
                for (int c = 0; c < 32; c += 2)
                    *(__half2*)(dst + c) = __floats2half2_rn(0.f, 0.f);
            }
        }
        // ---- stage B chunk: 64 rows (k) x 128 cols (n), fp32 -> fp16 ----
        {
            const int row   = tid >> 2;          // 0..63
            const int cbase = (tid & 3) * 32;    // 0,32,64,96
            const float* src = B + (size_t)(k0 + row) * NHID + bn + cbase;
            __half* dst = Bs + row * B_LD + cbase;
#pragma unroll
            for (int c = 0; c < 32; c += 4) {
                const float4 v = *(const float4*)(src + c);
                *(__half2*)(dst + c + 0) = __floats2half2_rn(v.x, v.y);
                *(__half2*)(dst + c + 2) = __floats2half2_rn(v.z, v.w);
            }
        }
        __syncthreads();

        // ---- HMMA ----
#pragma unroll
        for (int kk = 0; kk < GK_CHUNK; kk += 16) {
            wmma::fragment<wmma::matrix_a, 16, 16, 16, __half, wmma::row_major> af[2];
#pragma unroll
            for (int i = 0; i < 2; i++)
                wmma::load_matrix_sync(
                    af[i], As + (warp_m * 32 + i * 16) * A_LD + kk, A_LD);
#pragma unroll
            for (int j = 0; j < 4; j++) {
                wmma::fragment<wmma::matrix_b, 16, 16, 16, __half, wmma::row_major> bf;
                wmma::load_matrix_sync(
                    bf, Bs + kk * B_LD + warp_n * 64 + j * 16, B_LD);
#pragma unroll
                for (int i = 0; i < 2; i++)
                    wmma::mma_sync(acc[i][j], af[i], bf, acc[i][j]);
            }
        }
        __syncthreads();
    }

    // ---- epilogue: per-warp smem staging, two 32-col phases ----
    float* ws = (float*)smem_raw + wid * (32 * EPI_LD);
#pragma unroll
    for (int jp = 0; jp < 2; jp++) {
#pragma unroll
        for (int i = 0; i < 2; i++)
#pragma unroll
            for (int j2 = 0; j2 < 2; j2++)
                wmma::store_matrix_sync(ws + (i * 16) * EPI_LD + j2 * 16,
                                        acc[i][jp * 2 + j2], EPI_LD,
                                        wmma::mem_row_major);
        __syncwarp();
        const int gr = bm + warp_m * 32 + lane;
        if (gr < NN) {
            const float* srow = ws + lane * EPI_LD;
            __half2 hb[16];
#pragma unroll
            for (int g = 0; g < 8; g++) {
                const float4 v = *(const float4*)(srow + g * 4);
                hb[g * 2 + 0] = __floats2half2_rn(v.x, v.y);
                hb[g * 2 + 1] = __floats2half2_rn(v.z, v.w);
            }
            __half* op = g_xph + (size_t)gr * NHID + bn + warp_n * 64 + jp * 32;
            const uint4* src4 = (const uint4*)hb;
            *(uint4*)(op + 0)  = src4[0];
            *(uint4*)(op + 8)  = src4[1];
            *(uint4*)(op + 16) = src4[2];
            *(uint4*)(op + 24) = src4[3];
        }
        __syncwarp();
    }
}

// ---------------- K2: attention coefficients from fp16 xp ------------------
__global__ void acoef_kernel(const float* __restrict__ att_src,
                             const float* __restrict__ att_dst) {
    const int gwarp = (blockIdx.x * blockDim.x + threadIdx.x) >> 5;
    const int lane  = threadIdx.x & 31;
    if (gwarp >= NN) return;

    const uint4 hv = *(const uint4*)(g_xph + (size_t)gwarp * NHID + lane * 8);
    const __half2* hp = (const __half2*)&hv;
    const float2 f0 = __half22float2(hp[0]);
    const float2 f1 = __half22float2(hp[1]);
    const float2 f2 = __half22float2(hp[2]);
    const float2 f3 = __half22float2(hp[3]);

    const int head = lane >> 3;
    const int coff = (lane & 7) * 8;
    const float4* s4 = (const float4*)(att_src + head * CH + coff);
    const float4* d4 = (const float4*)(att_dst + head * CH + coff);
    const float4 s0 = s4[0], s1 = s4[1];
    const float4 d0 = d4[0], d1 = d4[1];

    float ps = f0.x * s0.x + f0.y * s0.y + f1.x * s0.z + f1.y * s0.w
             + f2.x * s1.x + f2.y * s1.y + f3.x * s1.z + f3.y * s1.w;
    float pd = f0.x * d0.x + f0.y * d0.y + f1.x * d0.z + f1.y * d0.w
             + f2.x * d1.x + f2.y * d1.y + f3.x * d1.z + f3.y * d1.w;

#pragma unroll
    for (int o = 1; o < 8; o <<= 1) {
        ps += __shfl_xor_sync(0xFFFFFFFFu, ps, o);
        pd += __shfl_xor_sync(0xFFFFFFFFu, pd, o);
    }
    if ((lane & 7) == 0) {
        g_asrc[gwarp * HEADS + head] = ps;
        g_adst[gwarp * HEADS + head] = pd;
    }
}

// ---------------- K3: degree histogram -------------------------------------
__global__ void hist_kernel(const int* __restrict__ ei) {
    const int e = blockIdx.x * blockDim.x + threadIdx.x;
    if (e >= ETOT) return;
    const int d = (e < EE) ? ei[EE + e] : (e - EE);
    atomicAdd(g_deg + d, 1);
}

// ---------------- K4: exclusive scan -> row_ptr (single block) -------------
#define SCAN_T 1024
__global__ void scan_kernel() {
    __shared__ int ssum[SCAN_T];
    const int t = threadIdx.x;
    const int chunk = (NN + SCAN_T - 1) / SCAN_T;   // 49
    const int lo = t * chunk;
    const int hi = min(lo + chunk, NN);

    int s = 0;
    for (int i = lo; i < hi; i++) s += g_deg[i];
    ssum[t] = s;
    __syncthreads();

    for (int off = 1; off < SCAN_T; off <<= 1) {
        int v = (t >= off) ? ssum[t - off] : 0;
        __syncthreads();
        ssum[t] += v;
        __syncthreads();
    }

    int run = (t == 0) ? 0 : ssum[t - 1];
    for (int i = lo; i < hi; i++) {
        g_rowptr[i] = run;
        g_wp[i] = run;
        run += g_deg[i];
    }
    if (t == SCAN_T - 1) g_rowptr[NN] = ETOT;
}

// ---------------- K5: CSR fill (src ids grouped by dst) --------------------
__global__ void fill_kernel(const int* __restrict__ ei) {
    const int e = blockIdx.x * blockDim.x + threadIdx.x;
    if (e >= ETOT) return;
    int s, d;
    if (e < EE) { s = ei[e]; d = ei[EE + e]; }
    else        { s = d = e - EE; }
    const int pos = atomicAdd(g_wp + d, 1);
    g_csrc[pos] = s;
}

// ---------------- K6: warp-per-dst SINGLE-PASS online softmax-aggregate ----
__global__ void agg_kernel(const float* __restrict__ bias) {
    const int w    = (int)(((size_t)blockIdx.x * blockDim.x + threadIdx.x) >> 5);
    const int lane = threadIdx.x & 31;
    if (w >= NN) return;
    const int d   = w;
    const int e0  = g_rowptr[d];
    const int cnt = g_rowptr[d + 1] - e0;   // >= 1 (self-loop)

    const int head  = lane >> 3;
    const float adh = g_adst[4 * d + head];
    const __half* xb = g_xph + (size_t)lane * 8;

    float m = -1e30f, s = 0.f;
    float a0 = 0.f, a1 = 0.f, a2 = 0.f, a3 = 0.f;
    float a4 = 0.f, a5 = 0.f, a6 = 0.f, a7 = 0.f;

#define AGG_PROC(HV, XV) do {                                               \
        const float l_ = lrelu((XV) + adh);                                  \
        float wgt_;                                                          \
        if (l_ > m) {                                                        \
            const float sc_ = __expf(m - l_);                                \
            s = s * sc_ + 1.f;                                               \
            a0 *= sc_; a1 *= sc_; a2 *= sc_; a3 *= sc_;                      \
            a4 *= sc_; a5 *= sc_; a6 *= sc_; a7 *= sc_;                      \
            m = l_; wgt_ = 1.f;                                              \
        } else {                                                             \
            wgt_ = __expf(l_ - m); s += wgt_;                                \
        }                                                                    \
        const __half2* hp_ = (const __half2*)&(HV);                          \
        const float2 f0_ = __half22float2(hp_[0]);                           \
        const float2 f1_ = __half22float2(hp_[1]);                           \
        const float2 f2_ = __half22float2(hp_[2]);                           \
        const float2 f3_ = __half22float2(hp_[3]);                           \
        a0 = fmaf(wgt_, f0_.x, a0); a1 = fmaf(wgt_, f0_.y, a1);              \
        a2 = fmaf(wgt_, f1_.x, a2); a3 = fmaf(wgt_, f1_.y, a3);              \
        a4 = fmaf(wgt_, f2_.x, a4); a5 = fmaf(wgt_, f2_.y, a5);              \
        a6 = fmaf(wgt_, f3_.x, a6); a7 = fmaf(wgt_, f3_.y, a7);              \
    } while (0)

    int sA = g_csrc[e0];
    uint4 hA = *(const uint4*)(xb + (size_t)sA * NHID);
    float xA = g_asrc[4 * sA + head];
    uint4 hB; float xB;
    if (cnt > 1) {
        const int sB = g_csrc[e0 + 1];
        hB = *(const uint4*)(xb + (size_t)sB * NHID);
        xB = g_asrc[4 * sB + head];
    }

    int i = 0;
    for (; i + 1 < cnt; i += 2) {
        const int i2 = (i + 2 < cnt) ? (i + 2) : (cnt - 1);
        const int i3 = (i + 3 < cnt) ? (i + 3) : (cnt - 1);
        const int s2 = g_csrc[e0 + i2];
        const int s3 = g_csrc[e0 + i3];
        const uint4 h2 = *(const uint4*)(xb + (size_t)s2 * NHID);
        const uint4 h3 = *(const uint4*)(xb + (size_t)s3 * NHID);
        const float x2 = g_asrc[4 * s2 + head];
        const float x3 = g_asrc[4 * s3 + head];

        AGG_PROC(hA, xA);
        AGG_PROC(hB, xB);

        hA = h2; xA = x2;
        hB = h3; xB = x3;
    }
    if (i < cnt) AGG_PROC(hA, xA);
#undef AGG_PROC

    const float inv = 1.f / (s + 1e-16f);
    const float4 b0 = *(const float4*)(bias + lane * 8);
    const float4 b1 = *(const float4*)(bias + lane * 8 + 4);
    float4 h0, h1;
    h0.x = fmaxf(fmaf(a0, inv, b0.x), 0.f);
    h0.y = fmaxf(fmaf(a1, inv, b0.y), 0.f);
    h0.z = fmaxf(fmaf(a2, inv, b0.z), 0.f);
    h0.w = fmaxf(fmaf(a3, inv, b0.w), 0.f);
    h1.x = fmaxf(fmaf(a4, inv, b1.x), 0.f);
    h1.y = fmaxf(fmaf(a5, inv, b1.y), 0.f);
    h1.z = fmaxf(fmaf(a6, inv, b1.z), 0.f);
    h1.w = fmaxf(fmaf(a7, inv, b1.w), 0.f);
    float4* op = (float4*)(g_acc + (size_t)d * NHID + lane * 8);
    op[0] = h0;
    op[1] = h1;
}

// ---------------- K7: per-graph max/mean pooling ---------------------------
#define POOL_NODES 256
__global__ void pool_kernel(const int* __restrict__ batch) {
    const int c  = threadIdx.x;               // channel 0..255
    const int n0 = blockIdx.x * POOL_NODES;
    const int n1 = min(n0 + POOL_NODES, NN);
    const int cnt_local = n1 - n0;

    __shared__ int sb[POOL_NODES];
    for (int i = threadIdx.x; i < cnt_local; i += blockDim.x)
        sb[i] = batch[n0 + i];
    __syncthreads();

    int curg = sb[0];
    float mx = 0.f, sm = 0.f;
    int cnt = 0;

    for (int i = 0; i < cnt_local; i++) {
        const int g = sb[i];
        if (g != curg) {
            atomicMax((int*)&g_pmax[curg * NHID + c], __float_as_int(mx));
            atomicAdd(&g_psum[curg * NHID + c], sm);
            if (c == 0) atomicAdd(&g_cnt[curg], cnt);
            curg = g; mx = 0.f; sm = 0.f; cnt = 0;
        }
        const float h = g_acc[(size_t)(n0 + i) * NHID + c];  // h >= 0
        mx = fmaxf(mx, h);
        sm += h;
        cnt++;
    }
    atomicMax((int*)&g_pmax[curg * NHID + c], __float_as_int(mx));
    atomicAdd(&g_psum[curg * NHID + c], sm);
    if (c == 0) atomicAdd(&g_cnt[curg], cnt);
}

// ---------------- K8: write output [NG, 2*NHID] ----------------------------
__global__ void final_kernel(float* __restrict__ out) {
    const int i = blockIdx.x * blockDim.x + threadIdx.x;
    if (i >= NG * NHID) return;
    const int g = i >> 8;
    const int c = i & 255;
    out[g * (2 * NHID) + c] = g_pmax[i];
    out[g * (2 * NHID) + NHID + c] = g_psum[i] / ((float)g_cnt[g] + 1e-16f);
}

// ---------------- launcher -------------------------------------------------
extern "C" void kernel_launch(void* const* d_in, const int* in_sizes, int n_in,
                              void* d_out, int out_size) {
    const float* x       = (const float*)d_in[0];
    const int*   ei      = (const int*)d_in[1];
    const int*   batch   = (const int*)d_in[2];
    const float* W       = (const float*)d_in[3];
    const float* att_src = (const float*)d_in[4];
    const float* att_dst = (const float*)d_in[5];
    const float* bias    = (const float*)d_in[6];
    float* out = (float*)d_out;

    zero_kernel<<<(NN + 255) / 256, 256>>>();
    {
        dim3 grid((NN + GM_TILE - 1) / GM_TILE, NHID / GN_TILE);
        gemm_kernel<<<grid, 256, GEMM_SMEM>>>(x, W);
    }
    acoef_kernel<<<(NN * 32 + 255) / 256, 256>>>(att_src, att_dst);
    hist_kernel<<<(ETOT + 255) / 256, 256>>>(ei);
    scan_kernel<<<1, SCAN_T>>>();
    fill_kernel<<<(ETOT + 255) / 256, 256>>>(ei);
    {
        long long total = (long long)NN * 32;
        agg_kernel<<<(int)((total + 255) / 256), 256>>>(bias);
    }
    pool_kernel<<<(NN + POOL_NODES - 1) / POOL_NODES, 256>>>(batch);
    final_kernel<<<(NG * NHID + 255) / 256, 256>>>(out);
}

// round 14
// speedup vs baseline: 1.8599x; 1.2078x over previous
#include <cuda_runtime.h>
#include <cuda_fp16.h>
#include <math_constants.h>
#include <mma.h>

using namespace nvcuda;

#define NN 50000
#define EE 800000
#define ETOT (EE + NN)
#define FIN 128
#define NHID 256
#define HEADS 4
#define CH 64
#define NG 16
#define NEG_SLOPE 0.2f

// ---------------- scratch (device globals; no allocation allowed) ----------
__device__ __half g_xph [(size_t)NN * NHID];   // x @ W (fp16)
__device__ float  g_acc [(size_t)NN * NHID];   // h = relu(agg + bias)
__device__ float  g_asrc[NN * HEADS];
__device__ float  g_adst[NN * HEADS];
__device__ int    g_deg [NN];
__device__ int    g_rowptr[NN + 1];
__device__ int    g_wp  [NN];
__device__ int    g_csrc[ETOT];
__device__ float  g_pmax[NG * NHID];
__device__ float  g_psum[NG * NHID];
__device__ int    g_cnt [NG];

// ---------------- helpers --------------------------------------------------
__device__ __forceinline__ float lrelu(float x) {
    return x > 0.f ? x : NEG_SLOPE * x;
}

// ---------------- K0: zero small scratch -----------------------------------
__global__ void zero_kernel() {
    int i = blockIdx.x * blockDim.x + threadIdx.x;
    if (i < NN) g_deg[i] = 0;
    if (i < NG * NHID) { g_pmax[i] = 0.f; g_psum[i] = 0.f; }
    if (i < NG) g_cnt[i] = 0;
}

// ---------------- K1: tensor-core GEMM + fused attention coefficients ------
// Block tile 128x128, K-chunks of 64, 8 warps (4x2), warp tile 32x64.
// Each warp's 64-col tile == exactly one attention head, so the epilogue
// computes the full (row, head) a_src/a_dst dots in registers (no atomics)
// from fp32 accumulators, then stores fp16 xph.
#define GM_TILE 128
#define GN_TILE 128
#define GK_CHUNK 64
#define A_LD 72      // 64 + 8 halves
#define B_LD 136     // 128 + 8 halves
#define EPI_LD 36    // 32 + 4 floats
#define GEMM_SMEM 36864

__global__ void __launch_bounds__(256, 2)
gemm_kernel(const float* __restrict__ A, const float* __restrict__ B,
            const float* __restrict__ att_src, const float* __restrict__ att_dst) {
    extern __shared__ unsigned char smem_raw[];
    __half* As = (__half*)smem_raw;                        // [128][A_LD]
    __half* Bs = (__half*)(smem_raw + 128 * A_LD * 2);     // [64][B_LD]

    const int tid  = threadIdx.x;
    const int wid  = tid >> 5;
    const int lane = tid & 31;
    const int warp_m = wid >> 1;       // 0..3
    const int warp_n = wid & 1;        // 0..1
    const int bm = blockIdx.x * GM_TILE;
    const int bn = blockIdx.y * GN_TILE;
    const int head = (bn >> 6) + warp_n;   // this warp's head (0..3)

    wmma::fragment<wmma::accumulator, 16, 16, 16, float> acc[2][4];
#pragma unroll
    for (int i = 0; i < 2; i++)
#pragma unroll
        for (int j = 0; j < 4; j++) wmma::fill_fragment(acc[i][j], 0.f);

    for (int k0 = 0; k0 < FIN; k0 += GK_CHUNK) {
        // ---- stage A chunk: 128 rows x 64 cols, fp32 -> fp16 ----
        {
            const int row   = tid >> 1;          // 0..127
            const int cbase = (tid & 1) * 32;    // 0 or 32
            const int gr = bm + row;
            __half* dst = As + row * A_LD + cbase;
            if (gr < NN) {
                const float* src = A + (size_t)gr * FIN + k0 + cbase;
#pragma unroll
                for (int c = 0; c < 32; c += 4) {
                    const float4 v = *(const float4*)(src + c);
                    *(__half2*)(dst + c + 0) = __floats2half2_rn(v.x, v.y);
                    *(__half2*)(dst + c + 2) = __floats2half2_rn(v.z, v.w);
                }
            } else {
#pragma unroll
                for (int c = 0; c < 32; c += 2)
                    *(__half2*)(dst + c) = __floats2half2_rn(0.f, 0.f);
            }
        }
        // ---- stage B chunk: 64 rows (k) x 128 cols (n), fp32 -> fp16 ----
        {
            const int row   = tid >> 2;          // 0..63
            const int cbase = (tid & 3) * 32;    // 0,32,64,96
            const float* src = B + (size_t)(k0 + row) * NHID + bn + cbase;
            __half* dst = Bs + row * B_LD + cbase;
#pragma unroll
            for (int c = 0; c < 32; c += 4) {
                const float4 v = *(const float4*)(src + c);
                *(__half2*)(dst + c + 0) = __floats2half2_rn(v.x, v.y);
                *(__half2*)(dst + c + 2) = __floats2half2_rn(v.z, v.w);
            }
        }
        __syncthreads();

        // ---- HMMA ----
#pragma unroll
        for (int kk = 0; kk < GK_CHUNK; kk += 16) {
            wmma::fragment<wmma::matrix_a, 16, 16, 16, __half, wmma::row_major> af[2];
#pragma unroll
            for (int i = 0; i < 2; i++)
                wmma::load_matrix_sync(
                    af[i], As + (warp_m * 32 + i * 16) * A_LD + kk, A_LD);
#pragma unroll
            for (int j = 0; j < 4; j++) {
                wmma::fragment<wmma::matrix_b, 16, 16, 16, __half, wmma::row_major> bf;
                wmma::load_matrix_sync(
                    bf, Bs + kk * B_LD + warp_n * 64 + j * 16, B_LD);
#pragma unroll
                for (int i = 0; i < 2; i++)
                    wmma::mma_sync(acc[i][j], af[i], bf, acc[i][j]);
            }
        }
        __syncthreads();
    }

    // ---- epilogue: per-warp smem staging, two 32-col phases ----
    // Lane owns row gr; across both phases it sees this head's full 64 cols,
    // so it accumulates the complete a_src/a_dst dots in registers.
    float* ws = (float*)smem_raw + wid * (32 * EPI_LD);
    const int gr = bm + warp_m * 32 + lane;
    float dot_s = 0.f, dot_d = 0.f;
#pragma unroll
    for (int jp = 0; jp < 2; jp++) {
#pragma unroll
        for (int i = 0; i < 2; i++)
#pragma unroll
            for (int j2 = 0; j2 < 2; j2++)
                wmma::store_matrix_sync(ws + (i * 16) * EPI_LD + j2 * 16,
                                        acc[i][jp * 2 + j2], EPI_LD,
                                        wmma::mem_row_major);
        __syncwarp();
        if (gr < NN) {
            const float* srow = ws + lane * EPI_LD;
            const float* atts = att_src + head * CH + jp * 32;
            const float* attd = att_dst + head * CH + jp * 32;
            __half2 hb[16];
#pragma unroll
            for (int g = 0; g < 8; g++) {
                const float4 v  = *(const float4*)(srow + g * 4);
                const float4 sa = *(const float4*)(atts + g * 4);
                const float4 da = *(const float4*)(attd + g * 4);
                dot_s += v.x * sa.x + v.y * sa.y + v.z * sa.z + v.w * sa.w;
                dot_d += v.x * da.x + v.y * da.y + v.z * da.z + v.w * da.w;
                hb[g * 2 + 0] = __floats2half2_rn(v.x, v.y);
                hb[g * 2 + 1] = __floats2half2_rn(v.z, v.w);
            }
            __half* op = g_xph + (size_t)gr * NHID + bn + warp_n * 64 + jp * 32;
            const uint4* src4 = (const uint4*)hb;
            *(uint4*)(op + 0)  = src4[0];
            *(uint4*)(op + 8)  = src4[1];
            *(uint4*)(op + 16) = src4[2];
            *(uint4*)(op + 24) = src4[3];
        }
        __syncwarp();
    }
    if (gr < NN) {
        g_asrc[gr * HEADS + head] = dot_s;
        g_adst[gr * HEADS + head] = dot_d;
    }
}

// ---------------- K2: degree histogram -------------------------------------
__global__ void hist_kernel(const int* __restrict__ ei) {
    const int e = blockIdx.x * blockDim.x + threadIdx.x;
    if (e >= ETOT) return;
    const int d = (e < EE) ? ei[EE + e] : (e - EE);
    atomicAdd(g_deg + d, 1);
}

// ---------------- K3: exclusive scan -> row_ptr (single block, int4) -------
#define SCAN_T 1024
#define SCAN_CHUNK 52   // 13 x int4; 1024*52 >= 50000
__global__ void scan_kernel() {
    __shared__ int ssum[SCAN_T];
    const int t  = threadIdx.x;
    const int lo = t * SCAN_CHUNK;
    const int hi = min(lo + SCAN_CHUNK, NN);

    int s = 0;
    if (lo + SCAN_CHUNK <= NN) {
        const int4* p = (const int4*)(g_deg + lo);
#pragma unroll
        for (int i = 0; i < 13; i++) {
            const int4 v = p[i];
            s += v.x + v.y + v.z + v.w;
        }
    } else {
        for (int i = lo; i < hi; i++) s += g_deg[i];
    }
    ssum[t] = s;
    __syncthreads();

    for (int off = 1; off < SCAN_T; off <<= 1) {
        int v = (t >= off) ? ssum[t - off] : 0;
        __syncthreads();
        ssum[t] += v;
        __syncthreads();
    }

    int run = (t == 0) ? 0 : ssum[t - 1];
    if (lo + SCAN_CHUNK <= NN) {
        const int4* p = (const int4*)(g_deg + lo);
#pragma unroll
        for (int i = 0; i < 13; i++) {
            const int4 v = p[i];
            int4 r;
            r.x = run; run += v.x;
            r.y = run; run += v.y;
            r.z = run; run += v.z;
            r.w = run; run += v.w;
            *(int4*)(g_rowptr + lo + i * 4) = r;
            *(int4*)(g_wp     + lo + i * 4) = r;
        }
    } else {
        for (int i = lo; i < hi; i++) {
            g_rowptr[i] = run;
            g_wp[i] = run;
            run += g_deg[i];
        }
    }
    if (t == 0) g_rowptr[NN] = ETOT;
}

// ---------------- K4: CSR fill (src ids grouped by dst) --------------------
__global__ void fill_kernel(const int* __restrict__ ei) {
    const int e = blockIdx.x * blockDim.x + threadIdx.x;
    if (e >= ETOT) return;
    int s, d;
    if (e < EE) { s = ei[e]; d = ei[EE + e]; }
    else        { s = d = e - EE; }
    const int pos = atomicAdd(g_wp + d, 1);
    g_csrc[pos] = s;
}

// ---------------- K5: warp-per-dst SINGLE-PASS online softmax-aggregate ----
__global__ void agg_kernel(const float* __restrict__ bias) {
    const int w    = (int)(((size_t)blockIdx.x * blockDim.x + threadIdx.x) >> 5);
    const int lane = threadIdx.x & 31;
    if (w >= NN) return;
    const int d   = w;
    const int e0  = g_rowptr[d];
    const int cnt = g_rowptr[d + 1] - e0;   // >= 1 (self-loop)

    const int head  = lane >> 3;
    const float adh = g_adst[4 * d + head];
    const __half* xb = g_xph + (size_t)lane * 8;

    float m = -1e30f, s = 0.f;
    float a0 = 0.f, a1 = 0.f, a2 = 0.f, a3 = 0.f;
    float a4 = 0.f, a5 = 0.f, a6 = 0.f, a7 = 0.f;

#define AGG_PROC(HV, XV) do {                                               \
        const float l_ = lrelu((XV) + adh);                                  \
        float wgt_;                                                          \
        if (l_ > m) {                                                        \
            const float sc_ = __expf(m - l_);                                \
            s = s * sc_ + 1.f;                                               \
            a0 *= sc_; a1 *= sc_; a2 *= sc_; a3 *= sc_;                      \
            a4 *= sc_; a5 *= sc_; a6 *= sc_; a7 *= sc_;                      \
            m = l_; wgt_ = 1.f;                                              \
        } else {                                                             \
            wgt_ = __expf(l_ - m); s += wgt_;                                \
        }                                                                    \
        const __half2* hp_ = (const __half2*)&(HV);                          \
        const float2 f0_ = __half22float2(hp_[0]);                           \
        const float2 f1_ = __half22float2(hp_[1]);                           \
        const float2 f2_ = __half22float2(hp_[2]);                           \
        const float2 f3_ = __half22float2(hp_[3]);                           \
        a0 = fmaf(wgt_, f0_.x, a0); a1 = fmaf(wgt_, f0_.y, a1);              \
        a2 = fmaf(wgt_, f1_.x, a2); a3 = fmaf(wgt_, f1_.y, a3);              \
        a4 = fmaf(wgt_, f2_.x, a4); a5 = fmaf(wgt_, f2_.y, a5);              \
        a6 = fmaf(wgt_, f3_.x, a6); a7 = fmaf(wgt_, f3_.y, a7);              \
    } while (0)

    int sA = g_csrc[e0];
    uint4 hA = *(const uint4*)(xb + (size_t)sA * NHID);
    float xA = g_asrc[4 * sA + head];
    uint4 hB; float xB;
    if (cnt > 1) {
        const int sB = g_csrc[e0 + 1];
        hB = *(const uint4*)(xb + (size_t)sB * NHID);
        xB = g_asrc[4 * sB + head];
    }

    int i = 0;
    for (; i + 1 < cnt; i += 2) {
        const int i2 = (i + 2 < cnt) ? (i + 2) : (cnt - 1);
        const int i3 = (i + 3 < cnt) ? (i + 3) : (cnt - 1);
        const int s2 = g_csrc[e0 + i2];
        const int s3 = g_csrc[e0 + i3];
        const uint4 h2 = *(const uint4*)(xb + (size_t)s2 * NHID);
        const uint4 h3 = *(const uint4*)(xb + (size_t)s3 * NHID);
        const float x2 = g_asrc[4 * s2 + head];
        const float x3 = g_asrc[4 * s3 + head];

        AGG_PROC(hA, xA);
        AGG_PROC(hB, xB);

        hA = h2; xA = x2;
        hB = h3; xB = x3;
    }
    if (i < cnt) AGG_PROC(hA, xA);
#undef AGG_PROC

    const float inv = 1.f / (s + 1e-16f);
    const float4 b0 = *(const float4*)(bias + lane * 8);
    const float4 b1 = *(const float4*)(bias + lane * 8 + 4);
    float4 h0, h1;
    h0.x = fmaxf(fmaf(a0, inv, b0.x), 0.f);
    h0.y = fmaxf(fmaf(a1, inv, b0.y), 0.f);
    h0.z = fmaxf(fmaf(a2, inv, b0.z), 0.f);
    h0.w = fmaxf(fmaf(a3, inv, b0.w), 0.f);
    h1.x = fmaxf(fmaf(a4, inv, b1.x), 0.f);
    h1.y = fmaxf(fmaf(a5, inv, b1.y), 0.f);
    h1.z = fmaxf(fmaf(a6, inv, b1.z), 0.f);
    h1.w = fmaxf(fmaf(a7, inv, b1.w), 0.f);
    float4* op = (float4*)(g_acc + (size_t)d * NHID + lane * 8);
    op[0] = h0;
    op[1] = h1;
}

// ---------------- K6: per-graph max/mean pooling ---------------------------
#define POOL_NODES 256
__global__ void pool_kernel(const int* __restrict__ batch) {
    const int c  = threadIdx.x;               // channel 0..255
    const int n0 = blockIdx.x * POOL_NODES;
    const int n1 = min(n0 + POOL_NODES, NN);
    const int cnt_local = n1 - n0;

    __shared__ int sb[POOL_NODES];
    for (int i = threadIdx.x; i < cnt_local; i += blockDim.x)
        sb[i] = batch[n0 + i];
    __syncthreads();

    int curg = sb[0];
    float mx = 0.f, sm = 0.f;
    int cnt = 0;

    for (int i = 0; i < cnt_local; i++) {
        const int g = sb[i];
        if (g != curg) {
            atomicMax((int*)&g_pmax[curg * NHID + c], __float_as_int(mx));
            atomicAdd(&g_psum[curg * NHID + c], sm);
            if (c == 0) atomicAdd(&g_cnt[curg], cnt);
            curg = g; mx = 0.f; sm = 0.f; cnt = 0;
        }
        const float h = g_acc[(size_t)(n0 + i) * NHID + c];  // h >= 0
        mx = fmaxf(mx, h);
        sm += h;
        cnt++;
    }
    atomicMax((int*)&g_pmax[curg * NHID + c], __float_as_int(mx));
    atomicAdd(&g_psum[curg * NHID + c], sm);
    if (c == 0) atomicAdd(&g_cnt[curg], cnt);
}

// ---------------- K7: write output [NG, 2*NHID] ----------------------------
__global__ void final_kernel(float* __restrict__ out) {
    const int i = blockIdx.x * blockDim.x + threadIdx.x;
    if (i >= NG * NHID) return;
    const int g = i >> 8;
    const int c = i & 255;
    out[g * (2 * NHID) + c] = g_pmax[i];
    out[g * (2 * NHID) + NHID + c] = g_psum[i] / ((float)g_cnt[g] + 1e-16f);
}

// ---------------- launcher -------------------------------------------------
extern "C" void kernel_launch(void* const* d_in, const int* in_sizes, int n_in,
                              void* d_out, int out_size) {
    const float* x       = (const float*)d_in[0];
    const int*   ei      = (const int*)d_in[1];
    const int*   batch   = (const int*)d_in[2];
    const float* W       = (const float*)d_in[3];
    const float* att_src = (const float*)d_in[4];
    const float* att_dst = (const float*)d_in[5];
    const float* bias    = (const float*)d_in[6];
    float* out = (float*)d_out;

    zero_kernel<<<(NN + 255) / 256, 256>>>();                       // launch 0
    {
        dim3 grid((NN + GM_TILE - 1) / GM_TILE, NHID / GN_TILE);
        gemm_kernel<<<grid, 256, GEMM_SMEM>>>(x, W, att_src, att_dst); // 1
    }
    hist_kernel<<<(ETOT + 255) / 256, 256>>>(ei);                   // 2
    scan_kernel<<<1, SCAN_T>>>();                                   // 3
    fill_kernel<<<(ETOT + 255) / 256, 256>>>(ei);                   // 4
    {
        long long total = (long long)NN * 32;
        agg_kernel<<<(int)((total + 255) / 256), 256>>>(bias);      // 5 <- ncu
    }
    pool_kernel<<<(NN + POOL_NODES - 1) / POOL_NODES, 256>>>(batch); // 6
    final_kernel<<<(NG * NHID + 255) / 256, 256>>>(out);            // 7
}

// round 16
// speedup vs baseline: 1.8689x; 1.0049x over previous
#include <cuda_runtime.h>
#include <cuda_fp16.h>
#include <math_constants.h>
#include <mma.h>

using namespace nvcuda;

#define NN 50000
#define EE 800000
#define ETOT (EE + NN)
#define FIN 128
#define NHID 256
#define HEADS 4
#define CH 64
#define NG 16
#define NEG_SLOPE 0.2f

// ---------------- scratch (device globals; no allocation allowed) ----------
__device__ __half g_xph [(size_t)NN * NHID];   // x @ W (fp16)
__device__ float  g_acc [(size_t)NN * NHID];   // h = relu(agg + bias)
__device__ float  g_asrc[NN * HEADS];
__device__ float  g_adst[NN * HEADS];
__device__ int    g_deg [NN];
__device__ int    g_rowptr[NN + 1];
__device__ int    g_wp  [NN];
__device__ int    g_csrc[ETOT];
__device__ float  g_pmax[NG * NHID];
__device__ float  g_psum[NG * NHID];
__device__ int    g_cnt [NG];

// ---------------- helpers --------------------------------------------------
__device__ __forceinline__ float lrelu(float x) {
    return x > 0.f ? x : NEG_SLOPE * x;
}

// ---------------- K0: zero small scratch -----------------------------------
__global__ void zero_kernel() {
    int i = blockIdx.x * blockDim.x + threadIdx.x;
    if (i < NN) g_deg[i] = 0;
    if (i < NG * NHID) { g_pmax[i] = 0.f; g_psum[i] = 0.f; }
    if (i < NG) g_cnt[i] = 0;
}

// ---------------- K1: tensor-core GEMM + fused attention coefficients ------
#define GM_TILE 128
#define GN_TILE 128
#define GK_CHUNK 64
#define A_LD 72      // 64 + 8 halves
#define B_LD 136     // 128 + 8 halves
#define EPI_LD 36    // 32 + 4 floats
#define GEMM_SMEM 36864

__global__ void __launch_bounds__(256, 2)
gemm_kernel(const float* __restrict__ A, const float* __restrict__ B,
            const float* __restrict__ att_src, const float* __restrict__ att_dst) {
    extern __shared__ unsigned char smem_raw[];
    __half* As = (__half*)smem_raw;                        // [128][A_LD]
    __half* Bs = (__half*)(smem_raw + 128 * A_LD * 2);     // [64][B_LD]

    const int tid  = threadIdx.x;
    const int wid  = tid >> 5;
    const int lane = tid & 31;
    const int warp_m = wid >> 1;       // 0..3
    const int warp_n = wid & 1;        // 0..1
    const int bm = blockIdx.x * GM_TILE;
    const int bn = blockIdx.y * GN_TILE;
    const int head = (bn >> 6) + warp_n;   // this warp's head (0..3)

    wmma::fragment<wmma::accumulator, 16, 16, 16, float> acc[2][4];
#pragma unroll
    for (int i = 0; i < 2; i++)
#pragma unroll
        for (int j = 0; j < 4; j++) wmma::fill_fragment(acc[i][j], 0.f);

    for (int k0 = 0; k0 < FIN; k0 += GK_CHUNK) {
        // ---- stage A chunk: 128 rows x 64 cols, fp32 -> fp16 ----
        {
            const int row   = tid >> 1;          // 0..127
            const int cbase = (tid & 1) * 32;    // 0 or 32
            const int gr = bm + row;
            __half* dst = As + row * A_LD + cbase;
            if (gr < NN) {
                const float* src = A + (size_t)gr * FIN + k0 + cbase;
#pragma unroll
                for (int c = 0; c < 32; c += 4) {
                    const float4 v = *(const float4*)(src + c);
                    *(__half2*)(dst + c + 0) = __floats2half2_rn(v.x, v.y);
                    *(__half2*)(dst + c + 2) = __floats2half2_rn(v.z, v.w);
                }
            } else {
#pragma unroll
                for (int c = 0; c < 32; c += 2)
                    *(__half2*)(dst + c) = __floats2half2_rn(0.f, 0.f);
            }
        }
        // ---- stage B chunk: 64 rows (k) x 128 cols (n), fp32 -> fp16 ----
        {
            const int row   = tid >> 2;          // 0..63
            const int cbase = (tid & 3) * 32;    // 0,32,64,96
            const float* src = B + (size_t)(k0 + row) * NHID + bn + cbase;
            __half* dst = Bs + row * B_LD + cbase;
#pragma unroll
            for (int c = 0; c < 32; c += 4) {
                const float4 v = *(const float4*)(src + c);
                *(__half2*)(dst + c + 0) = __floats2half2_rn(v.x, v.y);
                *(__half2*)(dst + c + 2) = __floats2half2_rn(v.z, v.w);
            }
        }
        __syncthreads();

        // ---- HMMA ----
#pragma unroll
        for (int kk = 0; kk < GK_CHUNK; kk += 16) {
            wmma::fragment<wmma::matrix_a, 16, 16, 16, __half, wmma::row_major> af[2];
#pragma unroll
            for (int i = 0; i < 2; i++)
                wmma::load_matrix_sync(
                    af[i], As + (warp_m * 32 + i * 16) * A_LD + kk, A_LD);
#pragma unroll
            for (int j = 0; j < 4; j++) {
                wmma::fragment<wmma::matrix_b, 16, 16, 16, __half, wmma::row_major> bf;
                wmma::load_matrix_sync(
                    bf, Bs + kk * B_LD + warp_n * 64 + j * 16, B_LD);
#pragma unroll
                for (int i = 0; i < 2; i++)
                    wmma::mma_sync(acc[i][j], af[i], bf, acc[i][j]);
            }
        }
        __syncthreads();
    }

    // ---- epilogue: per-warp smem staging + fused a_src/a_dst dots ----
    float* ws = (float*)smem_raw + wid * (32 * EPI_LD);
    const int gr = bm + warp_m * 32 + lane;
    float dot_s = 0.f, dot_d = 0.f;
#pragma unroll
    for (int jp = 0; jp < 2; jp++) {
#pragma unroll
        for (int i = 0; i < 2; i++)
#pragma unroll
            for (int j2 = 0; j2 < 2; j2++)
                wmma::store_matrix_sync(ws + (i * 16) * EPI_LD + j2 * 16,
                                        acc[i][jp * 2 + j2], EPI_LD,
                                        wmma::mem_row_major);
        __syncwarp();
        if (gr < NN) {
            const float* srow = ws + lane * EPI_LD;
            const float* atts = att_src + head * CH + jp * 32;
            const float* attd = att_dst + head * CH + jp * 32;
            __half2 hb[16];
#pragma unroll
            for (int g = 0; g < 8; g++) {
                const float4 v  = *(const float4*)(srow + g * 4);
                const float4 sa = *(const float4*)(atts + g * 4);
                const float4 da = *(const float4*)(attd + g * 4);
                dot_s += v.x * sa.x + v.y * sa.y + v.z * sa.z + v.w * sa.w;
                dot_d += v.x * da.x + v.y * da.y + v.z * da.z + v.w * da.w;
                hb[g * 2 + 0] = __floats2half2_rn(v.x, v.y);
                hb[g * 2 + 1] = __floats2half2_rn(v.z, v.w);
            }
            __half* op = g_xph + (size_t)gr * NHID + bn + warp_n * 64 + jp * 32;
            const uint4* src4 = (const uint4*)hb;
            *(uint4*)(op + 0)  = src4[0];
            *(uint4*)(op + 8)  = src4[1];
            *(uint4*)(op + 16) = src4[2];
            *(uint4*)(op + 24) = src4[3];
        }
        __syncwarp();
    }
    if (gr < NN) {
        g_asrc[gr * HEADS + head] = dot_s;
        g_adst[gr * HEADS + head] = dot_d;
    }
}

// ---------------- K2: degree histogram -------------------------------------
__global__ void hist_kernel(const int* __restrict__ ei) {
    const int e = blockIdx.x * blockDim.x + threadIdx.x;
    if (e >= ETOT) return;
    const int d = (e < EE) ? ei[EE + e] : (e - EE);
    atomicAdd(g_deg + d, 1);
}

// ---------------- K3: exclusive scan -> row_ptr (warp-shuffle, 2 barriers) -
#define SCAN_T 1024
#define SCAN_CHUNK 52   // 13 x int4; 1024*52 >= 50000
__global__ void scan_kernel() {
    __shared__ int warp_tot[32];
    const int t    = threadIdx.x;
    const int lane = t & 31;
    const int wid  = t >> 5;
    const int lo   = t * SCAN_CHUNK;
    const int hi   = min(lo + SCAN_CHUNK, NN);

    // per-thread sum (vectorized)
    int s = 0;
    if (lo + SCAN_CHUNK <= NN) {
        const int4* p = (const int4*)(g_deg + lo);
#pragma unroll
        for (int i = 0; i < 13; i++) {
            const int4 v = p[i];
            s += v.x + v.y + v.z + v.w;
        }
    } else {
        for (int i = lo; i < hi; i++) s += g_deg[i];
    }

    // warp inclusive scan (5 shfl steps, no barriers)
    int inc = s;
#pragma unroll
    for (int o = 1; o < 32; o <<= 1) {
        const int v = __shfl_up_sync(0xFFFFFFFFu, inc, o);
        if (lane >= o) inc += v;
    }
    if (lane == 31) warp_tot[wid] = inc;
    __syncthreads();

    // warp 0 scans the 32 warp totals
    if (wid == 0) {
        int w = warp_tot[lane];
#pragma unroll
        for (int o = 1; o < 32; o <<= 1) {
            const int v = __shfl_up_sync(0xFFFFFFFFu, w, o);
            if (lane >= o) w += v;
        }
        warp_tot[lane] = w;
    }
    __syncthreads();

    // exclusive prefix for this thread
    int run = (wid > 0 ? warp_tot[wid - 1] : 0) + (inc - s);

    // write rowptr / wp
    if (lo + SCAN_CHUNK <= NN) {
        const int4* p = (const int4*)(g_deg + lo);
#pragma unroll
        for (int i = 0; i < 13; i++) {
            const int4 v = p[i];
            int4 r;
            r.x = run; run += v.x;
            r.y = run; run += v.y;
            r.z = run; run += v.z;
            r.w = run; run += v.w;
            *(int4*)(g_rowptr + lo + i * 4) = r;
            *(int4*)(g_wp     + lo + i * 4) = r;
        }
    } else {
        for (int i = lo; i < hi; i++) {
            g_rowptr[i] = run;
            g_wp[i] = run;
            run += g_deg[i];
        }
    }
    if (t == 0) g_rowptr[NN] = ETOT;
}

// ---------------- K4: CSR fill (src ids grouped by dst) --------------------
__global__ void fill_kernel(const int* __restrict__ ei) {
    const int e = blockIdx.x * blockDim.x + threadIdx.x;
    if (e >= ETOT) return;
    int s, d;
    if (e < EE) { s = ei[e]; d = ei[EE + e]; }
    else        { s = d = e - EE; }
    const int pos = atomicAdd(g_wp + d, 1);
    g_csrc[pos] = s;
}

// ---------------- K5: warp-per-dst SINGLE-PASS online softmax-aggregate ----
__global__ void agg_kernel(const float* __restrict__ bias) {
    const int w    = (int)(((size_t)blockIdx.x * blockDim.x + threadIdx.x) >> 5);
    const int lane = threadIdx.x & 31;
    if (w >= NN) return;
    const int d   = w;
    const int e0  = g_rowptr[d];
    const int cnt = g_rowptr[d + 1] - e0;   // >= 1 (self-loop)

    const int head  = lane >> 3;
    const float adh = g_adst[4 * d + head];
    const __half* xb = g_xph + (size_t)lane * 8;

    float m = -1e30f, s = 0.f;
    float a0 = 0.f, a1 = 0.f, a2 = 0.f, a3 = 0.f;
    float a4 = 0.f, a5 = 0.f, a6 = 0.f, a7 = 0.f;

#define AGG_PROC(HV, XV) do {                                               \
        const float l_ = lrelu((XV) + adh);                                  \
        float wgt_;                                                          \
        if (l_ > m) {                                                        \
            const float sc_ = __expf(m - l_);                                \
            s = s * sc_ + 1.f;                                               \
            a0 *= sc_; a1 *= sc_; a2 *= sc_; a3 *= sc_;                      \
            a4 *= sc_; a5 *= sc_; a6 *= sc_; a7 *= sc_;                      \
            m = l_; wgt_ = 1.f;                                              \
        } else {                                                             \
            wgt_ = __expf(l_ - m); s += wgt_;                                \
        }                                                                    \
        const __half2* hp_ = (const __half2*)&(HV);                          \
        const float2 f0_ = __half22float2(hp_[0]);                           \
        const float2 f1_ = __half22float2(hp_[1]);                           \
        const float2 f2_ = __half22float2(hp_[2]);                           \
        const float2 f3_ = __half22float2(hp_[3]);                           \
        a0 = fmaf(wgt_, f0_.x, a0); a1 = fmaf(wgt_, f0_.y, a1);              \
        a2 = fmaf(wgt_, f1_.x, a2); a3 = fmaf(wgt_, f1_.y, a3);              \
        a4 = fmaf(wgt_, f2_.x, a4); a5 = fmaf(wgt_, f2_.y, a5);              \
        a6 = fmaf(wgt_, f3_.x, a6); a7 = fmaf(wgt_, f3_.y, a7);              \
    } while (0)

    int sA = __ldg(g_csrc + e0);
    uint4 hA = __ldg((const uint4*)(xb + (size_t)sA * NHID));
    float xA = __ldg(g_asrc + 4 * sA + head);
    uint4 hB; float xB;
    if (cnt > 1) {
        const int sB = __ldg(g_csrc + e0 + 1);
        hB = __ldg((const uint4*)(xb + (size_t)sB * NHID));
        xB = __ldg(g_asrc + 4 * sB + head);
    }

    int i = 0;
    for (; i + 1 < cnt; i += 2) {
        const int i2 = (i + 2 < cnt) ? (i + 2) : (cnt - 1);
        const int i3 = (i + 3 < cnt) ? (i + 3) : (cnt - 1);
        const int s2 = __ldg(g_csrc + e0 + i2);
        const int s3 = __ldg(g_csrc + e0 + i3);
        const uint4 h2 = __ldg((const uint4*)(xb + (size_t)s2 * NHID));
        const uint4 h3 = __ldg((const uint4*)(xb + (size_t)s3 * NHID));
        const float x2 = __ldg(g_asrc + 4 * s2 + head);
        const float x3 = __ldg(g_asrc + 4 * s3 + head);

        AGG_PROC(hA, xA);
        AGG_PROC(hB, xB);

        hA = h2; xA = x2;
        hB = h3; xB = x3;
    }
    if (i < cnt) AGG_PROC(hA, xA);
#undef AGG_PROC

    const float inv = 1.f / (s + 1e-16f);
    const float4 b0 = *(const float4*)(bias + lane * 8);
    const float4 b1 = *(const float4*)(bias + lane * 8 + 4);
    float4 h0, h1;
    h0.x = fmaxf(fmaf(a0, inv, b0.x), 0.f);
    h0.y = fmaxf(fmaf(a1, inv, b0.y), 0.f);
    h0.z = fmaxf(fmaf(a2, inv, b0.z), 0.f);
    h0.w = fmaxf(fmaf(a3, inv, b0.w), 0.f);
    h1.x = fmaxf(fmaf(a4, inv, b1.x), 0.f);
    h1.y = fmaxf(fmaf(a5, inv, b1.y), 0.f);
    h1.z = fmaxf(fmaf(a6, inv, b1.z), 0.f);
    h1.w = fmaxf(fmaf(a7, inv, b1.w), 0.f);
    float4* op = (float4*)(g_acc + (size_t)d * NHID + lane * 8);
    op[0] = h0;
    op[1] = h1;
}

// ---------------- K6: per-graph max/mean pooling ---------------------------
#define POOL_NODES 256
__global__ void pool_kernel(const int* __restrict__ batch) {
    const int c  = threadIdx.x;               // channel 0..255
    const int n0 = blockIdx.x * POOL_NODES;
    const int n1 = min(n0 + POOL_NODES, NN);
    const int cnt_local = n1 - n0;

    __shared__ int sb[POOL_NODES];
    for (int i = threadIdx.x; i < cnt_local; i += blockDim.x)
        sb[i] = batch[n0 + i];
    __syncthreads();

    int curg = sb[0];
    float mx = 0.f, sm = 0.f;
    int cnt = 0;

    for (int i = 0; i < cnt_local; i++) {
        const int g = sb[i];
        if (g != curg) {
            atomicMax((int*)&g_pmax[curg * NHID + c], __float_as_int(mx));
            atomicAdd(&g_psum[curg * NHID + c], sm);
            if (c == 0) atomicAdd(&g_cnt[curg], cnt);
            curg = g; mx = 0.f; sm = 0.f; cnt = 0;
        }
        const float h = g_acc[(size_t)(n0 + i) * NHID + c];  // h >= 0
        mx = fmaxf(mx, h);
        sm += h;
        cnt++;
    }
    atomicMax((int*)&g_pmax[curg * NHID + c], __float_as_int(mx));
    atomicAdd(&g_psum[curg * NHID + c], sm);
    if (c == 0) atomicAdd(&g_cnt[curg], cnt);
}

// ---------------- K7: write output [NG, 2*NHID] ----------------------------
__global__ void final_kernel(float* __restrict__ out) {
    const int i = blockIdx.x * blockDim.x + threadIdx.x;
    if (i >= NG * NHID) return;
    const int g = i >> 8;
    const int c = i & 255;
    out[g * (2 * NHID) + c] = g_pmax[i];
    out[g * (2 * NHID) + NHID + c] = g_psum[i] / ((float)g_cnt[g] + 1e-16f);
}

// ---------------- launcher -------------------------------------------------
extern "C" void kernel_launch(void* const* d_in, const int* in_sizes, int n_in,
                              void* d_out, int out_size) {
    const float* x       = (const float*)d_in[0];
    const int*   ei      = (const int*)d_in[1];
    const int*   batch   = (const int*)d_in[2];
    const float* W       = (const float*)d_in[3];
    const float* att_src = (const float*)d_in[4];
    const float* att_dst = (const float*)d_in[5];
    const float* bias    = (const float*)d_in[6];
    float* out = (float*)d_out;

    zero_kernel<<<(NN + 255) / 256, 256>>>();
    {
        dim3 grid((NN + GM_TILE - 1) / GM_TILE, NHID / GN_TILE);
        gemm_kernel<<<grid, 256, GEMM_SMEM>>>(x, W, att_src, att_dst);
    }
    hist_kernel<<<(ETOT + 255) / 256, 256>>>(ei);
    scan_kernel<<<1, SCAN_T>>>();
    fill_kernel<<<(ETOT + 255) / 256, 256>>>(ei);
    {
        long long total = (long long)NN * 32;
        agg_kernel<<<(int)((total + 255) / 256), 256>>>(bias);
    }
    pool_kernel<<<(NN + POOL_NODES - 1) / POOL_NODES, 256>>>(batch);
    final_kernel<<<(NG * NHID + 255) / 256, 256>>>(out);
}